// round 11
// baseline (speedup 1.0000x reference)
#include <cuda_runtime.h>
#include <cuda_bf16.h>
#include <math.h>
#include <stdint.h>

#define BROWS 8192
#define DDIM  512
#define KDIM  4096
#define LSTEPS 16

#define GM 64
#define GN 256
#define NCB (KDIM / GN)        // 16 column blocks
#define NROWBLK (BROWS / GM)   // 128
#define NCHUNKS 16             // d-chunks of 32 (hi+lo staged together)
#define GTHREADS 256
#define STAGES 2

#define ROWB 144                           // 128B data (64 hi + 64 lo) + 16 pad
#define ABYTES (GM * ROWB)                 // 9216
#define BBYTES (GN * ROWB)                 // 36864
#define STAGEB (ABYTES + BBYTES)           // 46080
#define SMEM_DYN (STAGES * STAGEB)         // 92160

// ---------------- device state ----------------
__device__ __align__(128) float g_resid[BROWS * DDIM];
__device__ __align__(128) __nv_bfloat16 g_Abf[BROWS * 1024];  // [row][0:512)=hi,[512:1024)=lo
__device__ __align__(128) __nv_bfloat16 g_Bbf[KDIM * 1024];
__device__ float g_rnorm[BROWS];
__device__ float g_tnorm[BROWS];
__device__ float g_pA[4 * NCB * BROWS];
__device__ int   g_pS[4 * NCB * BROWS];

// ---------------- helpers ----------------
__device__ __forceinline__ uint32_t smem_u32(const void* p) {
    uint32_t a;
    asm("{ .reg .u64 t; cvta.to.shared.u64 t, %1; cvt.u32.u64 %0, t; }" : "=r"(a) : "l"(p));
    return a;
}
__device__ __forceinline__ void cpasync16(uint32_t dst, const void* src) {
    asm volatile("cp.async.cg.shared.global [%0], [%1], 16;" :: "r"(dst), "l"(src));
}
#define CP_COMMIT() asm volatile("cp.async.commit_group;" ::: "memory")

__device__ __forceinline__ void mma_bf16(float* d, const uint32_t* a, const uint32_t* b) {
    asm volatile(
        "mma.sync.aligned.m16n8k16.row.col.f32.bf16.bf16.f32 "
        "{%0,%1,%2,%3}, {%4,%5,%6,%7}, {%8,%9}, {%0,%1,%2,%3};"
        : "+f"(d[0]), "+f"(d[1]), "+f"(d[2]), "+f"(d[3])
        : "r"(a[0]), "r"(a[1]), "r"(a[2]), "r"(a[3]), "r"(b[0]), "r"(b[1]));
}

__device__ __forceinline__ void split_bf(float v, __nv_bfloat16& h, __nv_bfloat16& l) {
    h = __float2bfloat16(v);
    l = __float2bfloat16(v - __bfloat162float(h));
}

// ---------------- prep: split inputs into bf16 hi/lo, norms ----------------
__global__ __launch_bounds__(256)
void lex_prep(const float* __restrict__ targets, const float* __restrict__ codebook) {
    const int tid = threadIdx.x;
    const int m = tid >> 2, q = tid & 3;
    if (blockIdx.x < 128) {
        int row = blockIdx.x * 64 + m;
        const float* src = targets + (size_t)row * DDIM + q * 128;
        __nv_bfloat16* dst = g_Abf + (size_t)row * 1024 + q * 128;
        float sum = 0.f;
        #pragma unroll 8
        for (int i = 0; i < 128; ++i) {
            float v = src[i];
            sum += v * v;
            split_bf(v, dst[i], dst[512 + i]);
        }
        sum += __shfl_xor_sync(0xffffffffu, sum, 1);
        sum += __shfl_xor_sync(0xffffffffu, sum, 2);
        if (q == 0) { float n = sqrtf(sum); g_rnorm[row] = n; g_tnorm[row] = n; }
    } else {
        int row = (blockIdx.x - 128) * 64 + m;
        const float* src = codebook + (size_t)row * DDIM + q * 128;
        __nv_bfloat16* dst = g_Bbf + (size_t)row * 1024 + q * 128;
        #pragma unroll 8
        for (int i = 0; i < 128; ++i) {
            split_bf(src[i], dst[i], dst[512 + i]);
        }
    }
}

// ---------------- GEMM (bf16 triple) + top-4; 2 blocks/SM ----------------
__global__ __launch_bounds__(GTHREADS, 2)
void lex_gemm() {
    extern __shared__ char dsm[];
    __shared__ float s_cabs[2][GM][17];
    __shared__ int   s_csig[2][GM][17];

    const int tid = threadIdx.x;
    const int wid = tid >> 5;      // 0..7
    const int lane = tid & 31;
    const int tg = lane >> 2;      // 0..7
    const int tq = lane & 3;       // 0..3
    const int wm = wid >> 2;       // 0..1  (32-row group)
    const int wn = wid & 3;        // 0..3  (64-col group)
    const int rowblock = blockIdx.x >> 4;
    const int cb = blockIdx.x & 15;
    const int rowbase = rowblock * GM;
    const int colbase = cb * GN;
    const uint32_t sbase = smem_u32(dsm);

    auto issue = [&](int c) {
        const int dbase = c * 32;
        const uint32_t base = sbase + (uint32_t)(c & 1) * STAGEB;
        #pragma unroll
        for (int i = 0; i < 2; ++i) {
            int idx = tid + i * GTHREADS;     // 0..511
            int r = idx >> 3;
            int seg = (idx >> 2) & 1, c16 = idx & 3;
            cpasync16(base + (uint32_t)(r * ROWB + seg * 64 + c16 * 16),
                      g_Abf + (size_t)(rowbase + r) * 1024 + seg * 512 + dbase + c16 * 8);
        }
        #pragma unroll
        for (int i = 0; i < 8; ++i) {
            int idx = tid + i * GTHREADS;     // 0..2047
            int n = idx >> 3;
            int seg = (idx >> 2) & 1, c16 = idx & 3;
            cpasync16(base + ABYTES + (uint32_t)(n * ROWB + seg * 64 + c16 * 16),
                      g_Bbf + (size_t)(colbase + n) * 1024 + seg * 512 + dbase + c16 * 8);
        }
        CP_COMMIT();
    };

    float acc[2][8][4];
    #pragma unroll
    for (int i = 0; i < 2; ++i)
        #pragma unroll
        for (int j = 0; j < 8; ++j)
            #pragma unroll
            for (int r = 0; r < 4; ++r) acc[i][j][r] = 0.f;

    issue(0);

    for (int c = 0; c < NCHUNKS; ++c) {
        asm volatile("cp.async.wait_group 0;" ::: "memory");   // chunk c complete
        __syncthreads();    // visibility of c + all warps finished reading stage (c-1)&1
        if (c + 1 < NCHUNKS) issue(c + 1);   // into stage (c+1)&1 = (c-1)&1, now free

        const char* As = dsm + (size_t)(c & 1) * STAGEB;
        const char* Bs = As + ABYTES;

        #pragma unroll
        for (int ks = 0; ks < 2; ++ks) {
            const int koff = ks * 32;           // 16 bf16 = 32 bytes within 64B seg
            uint32_t ah[2][4], al[2][4];
            #pragma unroll
            for (int i = 0; i < 2; ++i) {
                const char* p = As + (wm * 32 + i * 16 + tg) * ROWB + koff + tq * 4;
                ah[i][0] = *(const uint32_t*)(p);
                ah[i][1] = *(const uint32_t*)(p + 8 * ROWB);
                ah[i][2] = *(const uint32_t*)(p + 16);
                ah[i][3] = *(const uint32_t*)(p + 8 * ROWB + 16);
                al[i][0] = *(const uint32_t*)(p + 64);
                al[i][1] = *(const uint32_t*)(p + 8 * ROWB + 64);
                al[i][2] = *(const uint32_t*)(p + 80);
                al[i][3] = *(const uint32_t*)(p + 8 * ROWB + 80);
            }
            uint32_t bh[8][2], bl[8][2];
            #pragma unroll
            for (int j = 0; j < 8; ++j) {
                const char* p = Bs + (wn * 64 + j * 8 + tg) * ROWB + koff + tq * 4;
                bh[j][0] = *(const uint32_t*)(p);
                bh[j][1] = *(const uint32_t*)(p + 16);
                bl[j][0] = *(const uint32_t*)(p + 64);
                bl[j][1] = *(const uint32_t*)(p + 80);
            }
            #pragma unroll
            for (int i = 0; i < 2; ++i)
                #pragma unroll
                for (int j = 0; j < 8; ++j) {
                    mma_bf16(acc[i][j], ah[i], bh[j]);   // hi*hi
                    mma_bf16(acc[i][j], al[i], bh[j]);   // lo*hi
                    mma_bf16(acc[i][j], ah[i], bl[j]);   // hi*lo
                }
        }
    }

    // ---- per-thread top-2 candidates per row-slot ----
    #pragma unroll
    for (int i = 0; i < 2; ++i) {
        #pragma unroll
        for (int h = 0; h < 2; ++h) {
            float a1 = -1.f, a2 = -1.f;
            int s1 = 0, s2 = 0;
            #pragma unroll
            for (int j = 0; j < 8; ++j) {
                #pragma unroll
                for (int cc = 0; cc < 2; ++cc) {
                    float v = acc[i][j][h * 2 + cc];
                    float a = fabsf(v);
                    int k = colbase + wn * 64 + j * 8 + tq * 2 + cc;
                    int sg = (v >= 0.f) ? k : -(k + 1);
                    if (a > a1) { a2 = a1; s2 = s1; a1 = a; s1 = sg; }
                    else if (a > a2) { a2 = a; s2 = sg; }
                }
            }
            int rl = wm * 32 + i * 16 + tg + 8 * h;
            s_cabs[0][rl][wn * 4 + tq] = a1;
            s_csig[0][rl][wn * 4 + tq] = s1;
            s_cabs[1][rl][wn * 4 + tq] = a2;
            s_csig[1][rl][wn * 4 + tq] = s2;
        }
    }
    __syncthreads();

    // ---- per-row merge 32 -> top-4, write candidates ----
    if (tid < GM) {
        float A_[4] = {-1.f, -1.f, -1.f, -1.f};
        int   S_[4] = {0, 0, 0, 0};
        #pragma unroll
        for (int t = 0; t < 16; ++t) {
            #pragma unroll
            for (int slot = 0; slot < 2; ++slot) {
                float a = s_cabs[slot][tid][t];
                int sg = s_csig[slot][tid][t];
                if (a > A_[3]) {
                    if (a > A_[0]) {
                        A_[3]=A_[2]; S_[3]=S_[2]; A_[2]=A_[1]; S_[2]=S_[1];
                        A_[1]=A_[0]; S_[1]=S_[0]; A_[0]=a; S_[0]=sg;
                    } else if (a > A_[1]) {
                        A_[3]=A_[2]; S_[3]=S_[2]; A_[2]=A_[1]; S_[2]=S_[1];
                        A_[1]=a; S_[1]=sg;
                    } else if (a > A_[2]) {
                        A_[3]=A_[2]; S_[3]=S_[2]; A_[2]=a; S_[2]=sg;
                    } else {
                        A_[3]=a; S_[3]=sg;
                    }
                }
            }
        }
        #pragma unroll
        for (int s = 0; s < 4; ++s) {
            g_pA[(cb * 4 + s) * BROWS + rowbase + tid] = A_[s];
            g_pS[(cb * 4 + s) * BROWS + rowbase + tid] = S_[s];
        }
    }
}

// ---------------- merge + exact fp32 rescore of top-4 + residual update ----------------
__global__ __launch_bounds__(256)
void lex_update(const float* __restrict__ targets, const float* __restrict__ codebook,
                float* __restrict__ out, int step, float decay) {
    __shared__ int   s_k[4][64];
    __shared__ int   s_act[64];
    __shared__ float s_coef[64];
    __shared__ int   s_kidx[64];
    const int tid = threadIdx.x;
    const int rowbase = blockIdx.x * 64;
    const float* src = (step == 0) ? targets : g_resid;

    if (tid < 64) {
        int row = rowbase + tid;
        float A_[4] = {-1.f, -1.f, -1.f, -1.f};
        int   K_[4] = {0, 0, 0, 0};
        #pragma unroll
        for (int cbi = 0; cbi < NCB; ++cbi) {
            #pragma unroll
            for (int slot = 0; slot < 4; ++slot) {
                float a = g_pA[(cbi * 4 + slot) * BROWS + row];
                int sg = g_pS[(cbi * 4 + slot) * BROWS + row];
                int k = (sg >= 0) ? sg : (-sg - 1);
                if (a > A_[3]) {
                    if (a > A_[0]) {
                        A_[3]=A_[2]; K_[3]=K_[2]; A_[2]=A_[1]; K_[2]=K_[1];
                        A_[1]=A_[0]; K_[1]=K_[0]; A_[0]=a; K_[0]=k;
                    } else if (a > A_[1]) {
                        A_[3]=A_[2]; K_[3]=K_[2]; A_[2]=A_[1]; K_[2]=K_[1];
                        A_[1]=a; K_[1]=k;
                    } else if (a > A_[2]) {
                        A_[3]=A_[2]; K_[3]=K_[2]; A_[2]=a; K_[2]=k;
                    } else {
                        A_[3]=a; K_[3]=k;
                    }
                }
            }
        }
        #pragma unroll
        for (int s = 0; s < 4; ++s) s_k[s][tid] = K_[s];
        s_act[tid] = (g_rnorm[row] >= 0.01f) && (g_tnorm[row] >= 1e-8f);
    }
    __syncthreads();

    const int m = tid >> 2, q = tid & 3;
    const int row = rowbase + m;
    const int k0 = s_k[0][m], k1 = s_k[1][m], k2 = s_k[2][m], k3 = s_k[3][m];
    {
        const float* rp = src + (size_t)row * DDIM + q * 128;
        const float* c0 = codebook + (size_t)k0 * DDIM + q * 128;
        const float* c1 = codebook + (size_t)k1 * DDIM + q * 128;
        const float* c2 = codebook + (size_t)k2 * DDIM + q * 128;
        const float* c3 = codebook + (size_t)k3 * DDIM + q * 128;
        float d0 = 0.f, d1 = 0.f, d2 = 0.f, d3 = 0.f;
        #pragma unroll 4
        for (int i = 0; i < 32; ++i) {
            float4 r4 = *(const float4*)(rp + i * 4);
            float4 v0 = *(const float4*)(c0 + i * 4);
            float4 v1 = *(const float4*)(c1 + i * 4);
            float4 v2 = *(const float4*)(c2 + i * 4);
            float4 v3 = *(const float4*)(c3 + i * 4);
            d0 += r4.x * v0.x + r4.y * v0.y + r4.z * v0.z + r4.w * v0.w;
            d1 += r4.x * v1.x + r4.y * v1.y + r4.z * v1.z + r4.w * v1.w;
            d2 += r4.x * v2.x + r4.y * v2.y + r4.z * v2.z + r4.w * v2.w;
            d3 += r4.x * v3.x + r4.y * v3.y + r4.z * v3.z + r4.w * v3.w;
        }
        d0 += __shfl_xor_sync(0xffffffffu, d0, 1); d0 += __shfl_xor_sync(0xffffffffu, d0, 2);
        d1 += __shfl_xor_sync(0xffffffffu, d1, 1); d1 += __shfl_xor_sync(0xffffffffu, d1, 2);
        d2 += __shfl_xor_sync(0xffffffffu, d2, 1); d2 += __shfl_xor_sync(0xffffffffu, d2, 2);
        d3 += __shfl_xor_sync(0xffffffffu, d3, 1); d3 += __shfl_xor_sync(0xffffffffu, d3, 2);
        if (q == 0) {
            float bD = d0; int bK = k0; float bA = fabsf(d0);
            float a1 = fabsf(d1);
            if (a1 > bA || (a1 == bA && k1 < bK)) { bA = a1; bD = d1; bK = k1; }
            float a2 = fabsf(d2);
            if (a2 > bA || (a2 == bA && k2 < bK)) { bA = a2; bD = d2; bK = k2; }
            float a3 = fabsf(d3);
            if (a3 > bA || (a3 == bA && k3 < bK)) { bA = a3; bD = d3; bK = k3; }
            int bS = (bD >= 0.f) ? bK : -(bK + 1);
            bool active = s_act[m];
            s_coef[m] = active ? ((bD >= 0.f) ? decay : -decay) : 0.f;
            s_kidx[m] = bK;
            out[(size_t)row * LSTEPS + step] = active ? (float)bS : 0.f;
            out[(size_t)BROWS * LSTEPS + (size_t)row * LSTEPS + step] = active ? 1.f : 0.f;
        }
    }
    __syncthreads();

    const bool last = (step == LSTEPS - 1);
    float* resout = out + 2 * (size_t)BROWS * LSTEPS;
    const float coef = s_coef[m];
    const int kk = s_kidx[m];
    const size_t base = (size_t)row * DDIM + q * 128;
    const size_t cbo = (size_t)kk * DDIM + q * 128;
    __nv_bfloat16* dst = g_Abf + (size_t)row * 1024 + q * 128;
    float sum = 0.f;
    #pragma unroll 8
    for (int i = 0; i < 32; ++i) {
        float4 r4 = *(const float4*)(src + base + i * 4);
        float4 c4 = *(const float4*)(codebook + cbo + i * 4);
        float4 o;
        o.x = r4.x - coef * c4.x;
        o.y = r4.y - coef * c4.y;
        o.z = r4.z - coef * c4.z;
        o.w = r4.w - coef * c4.w;
        sum += o.x * o.x + o.y * o.y + o.z * o.z + o.w * o.w;
        *(float4*)(g_resid + base + i * 4) = o;
        split_bf(o.x, dst[i * 4 + 0], dst[512 + i * 4 + 0]);
        split_bf(o.y, dst[i * 4 + 1], dst[512 + i * 4 + 1]);
        split_bf(o.z, dst[i * 4 + 2], dst[512 + i * 4 + 2]);
        split_bf(o.w, dst[i * 4 + 3], dst[512 + i * 4 + 3]);
        if (last) *(float4*)(resout + base + i * 4) = o;
    }
    sum += __shfl_xor_sync(0xffffffffu, sum, 1);
    sum += __shfl_xor_sync(0xffffffffu, sum, 2);
    if (q == 0) g_rnorm[row] = sqrtf(sum);
}

extern "C" void kernel_launch(void* const* d_in, const int* in_sizes, int n_in,
                              void* d_out, int out_size) {
    (void)n_in; (void)out_size;
    const float* targets;
    const float* codebook;
    if (in_sizes[0] == BROWS * DDIM) {
        targets  = (const float*)d_in[0];
        codebook = (const float*)d_in[1];
    } else {
        targets  = (const float*)d_in[1];
        codebook = (const float*)d_in[0];
    }
    cudaFuncSetAttribute(lex_gemm, cudaFuncAttributeMaxDynamicSharedMemorySize, SMEM_DYN);
    float* out = (float*)d_out;

    lex_prep<<<192, 256>>>(targets, codebook);
    for (int s = 0; s < LSTEPS; ++s) {
        float decay = powf(0.95f, (float)(s + 1));
        lex_gemm<<<NROWBLK * NCB, GTHREADS, SMEM_DYN>>>();
        lex_update<<<BROWS / 64, 256>>>(targets, codebook, out, s, decay);
    }
}

// round 13
// speedup vs baseline: 1.3159x; 1.3159x over previous
#include <cuda_runtime.h>
#include <cuda_fp16.h>
#include <math.h>
#include <stdint.h>

#define BROWS 8192
#define DDIM  512
#define KDIM  4096
#define LSTEPS 16

#define GM 128
#define GN 256
#define NCB (KDIM / GN)        // 16 column blocks
#define NCHUNKS 16             // d-chunks of 32
#define GTHREADS 512
#define STAGES 3

#define AROWB 144                          // A: 64B hi + 64B lo + 16 pad
#define BROWB 80                           // B: 64B hi + 16 pad
#define ABYTES (GM * AROWB)                // 18432
#define BBYTES (GN * BROWB)                // 20480
#define STAGEB (ABYTES + BBYTES)           // 38912
#define SMEM_DYN (STAGES * STAGEB)         // 116736

// ---------------- device state ----------------
__device__ __align__(128) float g_resid[BROWS * DDIM];
__device__ __align__(128) __half g_Ah[BROWS * 1024];   // [row][0:512)=hi,[512:1024)=lo
__device__ __align__(128) __half g_Bh[KDIM * DDIM];    // codebook single fp16
__device__ float g_rnorm[BROWS];
__device__ float g_tnorm[BROWS];
__device__ float g_pA[4 * NCB * BROWS];
__device__ int   g_pS[4 * NCB * BROWS];

// ---------------- helpers ----------------
__device__ __forceinline__ uint32_t smem_u32(const void* p) {
    uint32_t a;
    asm("{ .reg .u64 t; cvta.to.shared.u64 t, %1; cvt.u32.u64 %0, t; }" : "=r"(a) : "l"(p));
    return a;
}
__device__ __forceinline__ void cpasync16(uint32_t dst, const void* src) {
    asm volatile("cp.async.cg.shared.global [%0], [%1], 16;" :: "r"(dst), "l"(src));
}
#define CP_COMMIT() asm volatile("cp.async.commit_group;" ::: "memory")

__device__ __forceinline__ void mma_f16(float* d, const uint32_t* a, const uint32_t* b) {
    asm volatile(
        "mma.sync.aligned.m16n8k16.row.col.f32.f16.f16.f32 "
        "{%0,%1,%2,%3}, {%4,%5,%6,%7}, {%8,%9}, {%0,%1,%2,%3};"
        : "+f"(d[0]), "+f"(d[1]), "+f"(d[2]), "+f"(d[3])
        : "r"(a[0]), "r"(a[1]), "r"(a[2]), "r"(a[3]), "r"(b[0]), "r"(b[1]));
}

__device__ __forceinline__ void split_h(float v, __half& h, __half& l) {
    h = __float2half(v);
    l = __float2half(v - __half2float(h));
}

// ---------------- prep: A -> fp16 hi/lo, B -> fp16, norms ----------------
__global__ __launch_bounds__(256)
void lex_prep(const float* __restrict__ targets, const float* __restrict__ codebook) {
    const int tid = threadIdx.x;
    const int m = tid >> 2, q = tid & 3;
    if (blockIdx.x < 128) {
        int row = blockIdx.x * 64 + m;
        const float* src = targets + (size_t)row * DDIM + q * 128;
        __half* dst = g_Ah + (size_t)row * 1024 + q * 128;
        float sum = 0.f;
        #pragma unroll 8
        for (int i = 0; i < 128; ++i) {
            float v = src[i];
            sum += v * v;
            split_h(v, dst[i], dst[512 + i]);
        }
        sum += __shfl_xor_sync(0xffffffffu, sum, 1);
        sum += __shfl_xor_sync(0xffffffffu, sum, 2);
        if (q == 0) { float n = sqrtf(sum); g_rnorm[row] = n; g_tnorm[row] = n; }
    } else {
        int row = (blockIdx.x - 128) * 64 + m;
        const float* src = codebook + (size_t)row * DDIM + q * 128;
        __half* dst = g_Bh + (size_t)row * DDIM + q * 128;
        #pragma unroll 8
        for (int i = 0; i < 128; ++i) {
            dst[i] = __float2half(src[i]);
        }
    }
}

// ---------------- GEMM (fp16 2-pass) + top-4 candidates ----------------
__global__ __launch_bounds__(GTHREADS, 1)
void lex_gemm() {
    extern __shared__ char dsm[];
    __shared__ float s_cabs[2][GM][17];
    __shared__ int   s_csig[2][GM][17];

    const int tid = threadIdx.x;
    const int wid = tid >> 5;      // 0..15
    const int lane = tid & 31;
    const int tg = lane >> 2;      // 0..7
    const int tq = lane & 3;       // 0..3
    const int wm = wid >> 2;       // 0..3  (32-row group)
    const int wn = wid & 3;        // 0..3  (64-col group)
    const int rowblock = blockIdx.x >> 4;
    const int cb = blockIdx.x & 15;
    const int rowbase = rowblock * GM;
    const int colbase = cb * GN;
    const uint32_t sbase = smem_u32(dsm);

    auto issue = [&](int c) {
        const int dbase = c * 32;
        const uint32_t base = sbase + (uint32_t)(c % STAGES) * STAGEB;
        // A: 128 rows x (64B hi + 64B lo) = 16 KB -> 1024 cp16 -> 2 iters
        #pragma unroll
        for (int i = 0; i < 2; ++i) {
            int idx = tid + i * GTHREADS;     // 0..1023
            int r = idx >> 3;
            int seg = (idx >> 2) & 1, c16 = idx & 3;
            cpasync16(base + (uint32_t)(r * AROWB + seg * 64 + c16 * 16),
                      g_Ah + (size_t)(rowbase + r) * 1024 + seg * 512 + dbase + c16 * 8);
        }
        // B: 256 rows x 64B = 16 KB -> 1024 cp16 -> 2 iters
        #pragma unroll
        for (int i = 0; i < 2; ++i) {
            int idx = tid + i * GTHREADS;     // 0..1023
            int n = idx >> 2, c16 = idx & 3;
            cpasync16(base + ABYTES + (uint32_t)(n * BROWB + c16 * 16),
                      g_Bh + (size_t)(colbase + n) * DDIM + dbase + c16 * 8);
        }
        CP_COMMIT();
    };

    float acc[2][8][4];
    #pragma unroll
    for (int i = 0; i < 2; ++i)
        #pragma unroll
        for (int j = 0; j < 8; ++j)
            #pragma unroll
            for (int r = 0; r < 4; ++r) acc[i][j][r] = 0.f;

    issue(0); issue(1);

    for (int c = 0; c < NCHUNKS; ++c) {
        asm volatile("cp.async.wait_group 1;" ::: "memory");
        __syncthreads();
        if (c + 2 < NCHUNKS) issue(c + 2);
        else CP_COMMIT();                       // keep group accounting uniform

        const char* As = dsm + (size_t)(c % STAGES) * STAGEB;
        const char* Bs = As + ABYTES;

        #pragma unroll
        for (int ks = 0; ks < 2; ++ks) {
            const int koff = ks * 32;           // 16 fp16 = 32 bytes
            uint32_t ah[2][4], al[2][4];
            #pragma unroll
            for (int i = 0; i < 2; ++i) {
                const char* p = As + (wm * 32 + i * 16 + tg) * AROWB + koff + tq * 4;
                ah[i][0] = *(const uint32_t*)(p);
                ah[i][1] = *(const uint32_t*)(p + 8 * AROWB);
                ah[i][2] = *(const uint32_t*)(p + 16);
                ah[i][3] = *(const uint32_t*)(p + 8 * AROWB + 16);
                al[i][0] = *(const uint32_t*)(p + 64);
                al[i][1] = *(const uint32_t*)(p + 8 * AROWB + 64);
                al[i][2] = *(const uint32_t*)(p + 80);
                al[i][3] = *(const uint32_t*)(p + 8 * AROWB + 80);
            }
            uint32_t bh[8][2];
            #pragma unroll
            for (int j = 0; j < 8; ++j) {
                const char* p = Bs + (wn * 64 + j * 8 + tg) * BROWB + koff + tq * 4;
                bh[j][0] = *(const uint32_t*)(p);
                bh[j][1] = *(const uint32_t*)(p + 16);
            }
            #pragma unroll
            for (int i = 0; i < 2; ++i)
                #pragma unroll
                for (int j = 0; j < 8; ++j) {
                    mma_f16(acc[i][j], ah[i], bh[j]);   // hi*b
                    mma_f16(acc[i][j], al[i], bh[j]);   // lo*b
                }
        }
    }

    // ---- per-thread top-2 candidates per row-slot ----
    #pragma unroll
    for (int i = 0; i < 2; ++i) {
        #pragma unroll
        for (int h = 0; h < 2; ++h) {
            float a1 = -1.f, a2 = -1.f;
            int s1 = 0, s2 = 0;
            #pragma unroll
            for (int j = 0; j < 8; ++j) {
                #pragma unroll
                for (int cc = 0; cc < 2; ++cc) {
                    float v = acc[i][j][h * 2 + cc];
                    float a = fabsf(v);
                    int k = colbase + wn * 64 + j * 8 + tq * 2 + cc;
                    int sg = (v >= 0.f) ? k : -(k + 1);
                    if (a > a1) { a2 = a1; s2 = s1; a1 = a; s1 = sg; }
                    else if (a > a2) { a2 = a; s2 = sg; }
                }
            }
            int rl = wm * 32 + i * 16 + tg + 8 * h;
            s_cabs[0][rl][wn * 4 + tq] = a1;
            s_csig[0][rl][wn * 4 + tq] = s1;
            s_cabs[1][rl][wn * 4 + tq] = a2;
            s_csig[1][rl][wn * 4 + tq] = s2;
        }
    }
    __syncthreads();

    // ---- per-row merge 32 -> top-4, write candidates ----
    if (tid < GM) {
        float A_[4] = {-1.f, -1.f, -1.f, -1.f};
        int   S_[4] = {0, 0, 0, 0};
        #pragma unroll
        for (int t = 0; t < 16; ++t) {
            #pragma unroll
            for (int slot = 0; slot < 2; ++slot) {
                float a = s_cabs[slot][tid][t];
                int sg = s_csig[slot][tid][t];
                if (a > A_[3]) {
                    if (a > A_[0]) {
                        A_[3]=A_[2]; S_[3]=S_[2]; A_[2]=A_[1]; S_[2]=S_[1];
                        A_[1]=A_[0]; S_[1]=S_[0]; A_[0]=a; S_[0]=sg;
                    } else if (a > A_[1]) {
                        A_[3]=A_[2]; S_[3]=S_[2]; A_[2]=A_[1]; S_[2]=S_[1];
                        A_[1]=a; S_[1]=sg;
                    } else if (a > A_[2]) {
                        A_[3]=A_[2]; S_[3]=S_[2]; A_[2]=a; S_[2]=sg;
                    } else {
                        A_[3]=a; S_[3]=sg;
                    }
                }
            }
        }
        #pragma unroll
        for (int s = 0; s < 4; ++s) {
            g_pA[(cb * 4 + s) * BROWS + rowbase + tid] = A_[s];
            g_pS[(cb * 4 + s) * BROWS + rowbase + tid] = S_[s];
        }
    }
}

// ---------------- merge + exact fp32 rescore of top-4 + residual update ----------------
__global__ __launch_bounds__(256)
void lex_update(const float* __restrict__ targets, const float* __restrict__ codebook,
                float* __restrict__ out, int step, float decay) {
    __shared__ int   s_k[4][64];
    __shared__ int   s_act[64];
    __shared__ float s_coef[64];
    __shared__ int   s_kidx[64];
    const int tid = threadIdx.x;
    const int rowbase = blockIdx.x * 64;
    const float* src = (step == 0) ? targets : g_resid;

    if (tid < 64) {
        int row = rowbase + tid;
        float A_[4] = {-1.f, -1.f, -1.f, -1.f};
        int   K_[4] = {0, 0, 0, 0};
        #pragma unroll
        for (int cbi = 0; cbi < NCB; ++cbi) {
            #pragma unroll
            for (int slot = 0; slot < 4; ++slot) {
                float a = g_pA[(cbi * 4 + slot) * BROWS + row];
                int sg = g_pS[(cbi * 4 + slot) * BROWS + row];
                int k = (sg >= 0) ? sg : (-sg - 1);
                if (a > A_[3]) {
                    if (a > A_[0]) {
                        A_[3]=A_[2]; K_[3]=K_[2]; A_[2]=A_[1]; K_[2]=K_[1];
                        A_[1]=A_[0]; K_[1]=K_[0]; A_[0]=a; K_[0]=k;
                    } else if (a > A_[1]) {
                        A_[3]=A_[2]; K_[3]=K_[2]; A_[2]=A_[1]; K_[2]=K_[1];
                        A_[1]=a; K_[1]=k;
                    } else if (a > A_[2]) {
                        A_[3]=A_[2]; K_[3]=K_[2]; A_[2]=a; K_[2]=k;
                    } else {
                        A_[3]=a; K_[3]=k;
                    }
                }
            }
        }
        #pragma unroll
        for (int s = 0; s < 4; ++s) s_k[s][tid] = K_[s];
        s_act[tid] = (g_rnorm[row] >= 0.01f) && (g_tnorm[row] >= 1e-8f);
    }
    __syncthreads();

    const int m = tid >> 2, q = tid & 3;
    const int row = rowbase + m;
    const int k0 = s_k[0][m], k1 = s_k[1][m], k2 = s_k[2][m], k3 = s_k[3][m];
    {
        const float* rp = src + (size_t)row * DDIM + q * 128;
        const float* c0 = codebook + (size_t)k0 * DDIM + q * 128;
        const float* c1 = codebook + (size_t)k1 * DDIM + q * 128;
        const float* c2 = codebook + (size_t)k2 * DDIM + q * 128;
        const float* c3 = codebook + (size_t)k3 * DDIM + q * 128;
        float d0 = 0.f, d1 = 0.f, d2 = 0.f, d3 = 0.f;
        #pragma unroll 4
        for (int i = 0; i < 32; ++i) {
            float4 r4 = *(const float4*)(rp + i * 4);
            float4 v0 = *(const float4*)(c0 + i * 4);
            float4 v1 = *(const float4*)(c1 + i * 4);
            float4 v2 = *(const float4*)(c2 + i * 4);
            float4 v3 = *(const float4*)(c3 + i * 4);
            d0 += r4.x * v0.x + r4.y * v0.y + r4.z * v0.z + r4.w * v0.w;
            d1 += r4.x * v1.x + r4.y * v1.y + r4.z * v1.z + r4.w * v1.w;
            d2 += r4.x * v2.x + r4.y * v2.y + r4.z * v2.z + r4.w * v2.w;
            d3 += r4.x * v3.x + r4.y * v3.y + r4.z * v3.z + r4.w * v3.w;
        }
        d0 += __shfl_xor_sync(0xffffffffu, d0, 1); d0 += __shfl_xor_sync(0xffffffffu, d0, 2);
        d1 += __shfl_xor_sync(0xffffffffu, d1, 1); d1 += __shfl_xor_sync(0xffffffffu, d1, 2);
        d2 += __shfl_xor_sync(0xffffffffu, d2, 1); d2 += __shfl_xor_sync(0xffffffffu, d2, 2);
        d3 += __shfl_xor_sync(0xffffffffu, d3, 1); d3 += __shfl_xor_sync(0xffffffffu, d3, 2);
        if (q == 0) {
            float bD = d0; int bK = k0; float bA = fabsf(d0);
            float a1 = fabsf(d1);
            if (a1 > bA || (a1 == bA && k1 < bK)) { bA = a1; bD = d1; bK = k1; }
            float a2 = fabsf(d2);
            if (a2 > bA || (a2 == bA && k2 < bK)) { bA = a2; bD = d2; bK = k2; }
            float a3 = fabsf(d3);
            if (a3 > bA || (a3 == bA && k3 < bK)) { bA = a3; bD = d3; bK = k3; }
            int bS = (bD >= 0.f) ? bK : -(bK + 1);
            bool active = s_act[m];
            s_coef[m] = active ? ((bD >= 0.f) ? decay : -decay) : 0.f;
            s_kidx[m] = bK;
            out[(size_t)row * LSTEPS + step] = active ? (float)bS : 0.f;
            out[(size_t)BROWS * LSTEPS + (size_t)row * LSTEPS + step] = active ? 1.f : 0.f;
        }
    }
    __syncthreads();

    const bool last = (step == LSTEPS - 1);
    float* resout = out + 2 * (size_t)BROWS * LSTEPS;
    const float coef = s_coef[m];
    const int kk = s_kidx[m];
    const size_t base = (size_t)row * DDIM + q * 128;
    const size_t cbo = (size_t)kk * DDIM + q * 128;
    __half* dst = g_Ah + (size_t)row * 1024 + q * 128;
    float sum = 0.f;
    #pragma unroll 8
    for (int i = 0; i < 32; ++i) {
        float4 r4 = *(const float4*)(src + base + i * 4);
        float4 c4 = *(const float4*)(codebook + cbo + i * 4);
        float4 o;
        o.x = r4.x - coef * c4.x;
        o.y = r4.y - coef * c4.y;
        o.z = r4.z - coef * c4.z;
        o.w = r4.w - coef * c4.w;
        sum += o.x * o.x + o.y * o.y + o.z * o.z + o.w * o.w;
        *(float4*)(g_resid + base + i * 4) = o;
        split_h(o.x, dst[i * 4 + 0], dst[512 + i * 4 + 0]);
        split_h(o.y, dst[i * 4 + 1], dst[512 + i * 4 + 1]);
        split_h(o.z, dst[i * 4 + 2], dst[512 + i * 4 + 2]);
        split_h(o.w, dst[i * 4 + 3], dst[512 + i * 4 + 3]);
        if (last) *(float4*)(resout + base + i * 4) = o;
    }
    sum += __shfl_xor_sync(0xffffffffu, sum, 1);
    sum += __shfl_xor_sync(0xffffffffu, sum, 2);
    if (q == 0) g_rnorm[row] = sqrtf(sum);
}

extern "C" void kernel_launch(void* const* d_in, const int* in_sizes, int n_in,
                              void* d_out, int out_size) {
    (void)n_in; (void)out_size;
    const float* targets;
    const float* codebook;
    if (in_sizes[0] == BROWS * DDIM) {
        targets  = (const float*)d_in[0];
        codebook = (const float*)d_in[1];
    } else {
        targets  = (const float*)d_in[1];
        codebook = (const float*)d_in[0];
    }
    cudaFuncSetAttribute(lex_gemm, cudaFuncAttributeMaxDynamicSharedMemorySize, SMEM_DYN);
    float* out = (float*)d_out;

    lex_prep<<<192, 256>>>(targets, codebook);
    for (int s = 0; s < LSTEPS; ++s) {
        float decay = powf(0.95f, (float)(s + 1));
        lex_gemm<<<(BROWS / GM) * NCB, GTHREADS, SMEM_DYN>>>();
        lex_update<<<BROWS / 64, 256>>>(targets, codebook, out, s, decay);
    }
}

// round 14
// speedup vs baseline: 1.8345x; 1.3941x over previous
#include <cuda_runtime.h>
#include <cuda_fp16.h>
#include <math.h>
#include <stdint.h>

#define BROWS 8192
#define DDIM  512
#define KDIM  4096
#define LSTEPS 16

#define GM 128
#define GN 256
#define NCB (KDIM / GN)        // 16 column blocks
#define NCHUNKS 16             // d-chunks of 32
#define GTHREADS 512
#define STAGES 3

#define AROWB 80                           // A: 64B + 16 pad
#define BROWB 80                           // B: 64B + 16 pad
#define ABYTES (GM * AROWB)                // 10240
#define BBYTES (GN * BROWB)                // 20480
#define STAGEB (ABYTES + BBYTES)           // 30720
#define SMEM_DYN (STAGES * STAGEB)         // 92160

// ---------------- device state ----------------
__device__ __align__(128) float g_resid[BROWS * DDIM];
__device__ __align__(128) __half g_Ah[BROWS * DDIM];   // residual single fp16
__device__ __align__(128) __half g_Bh[KDIM * DDIM];    // codebook single fp16
__device__ float g_rnorm[BROWS];
__device__ float g_tnorm[BROWS];
__device__ float g_pA[4 * NCB * BROWS];
__device__ int   g_pS[4 * NCB * BROWS];

// ---------------- helpers ----------------
__device__ __forceinline__ uint32_t smem_u32(const void* p) {
    uint32_t a;
    asm("{ .reg .u64 t; cvta.to.shared.u64 t, %1; cvt.u32.u64 %0, t; }" : "=r"(a) : "l"(p));
    return a;
}
__device__ __forceinline__ void cpasync16(uint32_t dst, const void* src) {
    asm volatile("cp.async.cg.shared.global [%0], [%1], 16;" :: "r"(dst), "l"(src));
}
#define CP_COMMIT() asm volatile("cp.async.commit_group;" ::: "memory")

__device__ __forceinline__ void mma_f16(float* d, const uint32_t* a, const uint32_t* b) {
    asm volatile(
        "mma.sync.aligned.m16n8k16.row.col.f32.f16.f16.f32 "
        "{%0,%1,%2,%3}, {%4,%5,%6,%7}, {%8,%9}, {%0,%1,%2,%3};"
        : "+f"(d[0]), "+f"(d[1]), "+f"(d[2]), "+f"(d[3])
        : "r"(a[0]), "r"(a[1]), "r"(a[2]), "r"(a[3]), "r"(b[0]), "r"(b[1]));
}

// ---------------- prep: A -> fp16, B -> fp16, norms ----------------
__global__ __launch_bounds__(256)
void lex_prep(const float* __restrict__ targets, const float* __restrict__ codebook) {
    const int tid = threadIdx.x;
    const int m = tid >> 2, q = tid & 3;
    if (blockIdx.x < 128) {
        int row = blockIdx.x * 64 + m;
        const float* src = targets + (size_t)row * DDIM + q * 128;
        __half* dst = g_Ah + (size_t)row * DDIM + q * 128;
        float sum = 0.f;
        #pragma unroll 8
        for (int i = 0; i < 128; ++i) {
            float v = src[i];
            sum += v * v;
            dst[i] = __float2half(v);
        }
        sum += __shfl_xor_sync(0xffffffffu, sum, 1);
        sum += __shfl_xor_sync(0xffffffffu, sum, 2);
        if (q == 0) { float n = sqrtf(sum); g_rnorm[row] = n; g_tnorm[row] = n; }
    } else {
        int row = (blockIdx.x - 128) * 64 + m;
        const float* src = codebook + (size_t)row * DDIM + q * 128;
        __half* dst = g_Bh + (size_t)row * DDIM + q * 128;
        #pragma unroll 8
        for (int i = 0; i < 128; ++i) {
            dst[i] = __float2half(src[i]);
        }
    }
}

// ---------------- GEMM (fp16 single-pass) + top-4 candidates ----------------
__global__ __launch_bounds__(GTHREADS, 1)
void lex_gemm() {
    extern __shared__ char dsm[];
    __shared__ float s_cabs[2][GM][17];
    __shared__ int   s_csig[2][GM][17];

    const int tid = threadIdx.x;
    const int wid = tid >> 5;      // 0..15
    const int lane = tid & 31;
    const int tg = lane >> 2;      // 0..7
    const int tq = lane & 3;       // 0..3
    const int wm = wid >> 2;       // 0..3  (32-row group)
    const int wn = wid & 3;        // 0..3  (64-col group)
    const int rowblock = blockIdx.x >> 4;
    const int cb = blockIdx.x & 15;
    const int rowbase = rowblock * GM;
    const int colbase = cb * GN;
    const uint32_t sbase = smem_u32(dsm);

    auto issue = [&](int c) {
        const int dbase = c * 32;
        const uint32_t base = sbase + (uint32_t)(c % STAGES) * STAGEB;
        // A: 128 rows x 64B = 8 KB -> 512 cp16 -> 1 iter
        {
            int r = tid >> 2, c16 = tid & 3;
            cpasync16(base + (uint32_t)(r * AROWB + c16 * 16),
                      g_Ah + (size_t)(rowbase + r) * DDIM + dbase + c16 * 8);
        }
        // B: 256 rows x 64B = 16 KB -> 1024 cp16 -> 2 iters
        #pragma unroll
        for (int i = 0; i < 2; ++i) {
            int idx = tid + i * GTHREADS;     // 0..1023
            int n = idx >> 2, c16 = idx & 3;
            cpasync16(base + ABYTES + (uint32_t)(n * BROWB + c16 * 16),
                      g_Bh + (size_t)(colbase + n) * DDIM + dbase + c16 * 8);
        }
        CP_COMMIT();
    };

    float acc[2][8][4];
    #pragma unroll
    for (int i = 0; i < 2; ++i)
        #pragma unroll
        for (int j = 0; j < 8; ++j)
            #pragma unroll
            for (int r = 0; r < 4; ++r) acc[i][j][r] = 0.f;

    issue(0); issue(1);

    for (int c = 0; c < NCHUNKS; ++c) {
        asm volatile("cp.async.wait_group 1;" ::: "memory");
        __syncthreads();
        if (c + 2 < NCHUNKS) issue(c + 2);
        else CP_COMMIT();                       // keep group accounting uniform

        const char* As = dsm + (size_t)(c % STAGES) * STAGEB;
        const char* Bs = As + ABYTES;

        #pragma unroll
        for (int ks = 0; ks < 2; ++ks) {
            const int koff = ks * 32;           // 16 fp16 = 32 bytes
            uint32_t ah[2][4];
            #pragma unroll
            for (int i = 0; i < 2; ++i) {
                const char* p = As + (wm * 32 + i * 16 + tg) * AROWB + koff + tq * 4;
                ah[i][0] = *(const uint32_t*)(p);
                ah[i][1] = *(const uint32_t*)(p + 8 * AROWB);
                ah[i][2] = *(const uint32_t*)(p + 16);
                ah[i][3] = *(const uint32_t*)(p + 8 * AROWB + 16);
            }
            uint32_t bh[8][2];
            #pragma unroll
            for (int j = 0; j < 8; ++j) {
                const char* p = Bs + (wn * 64 + j * 8 + tg) * BROWB + koff + tq * 4;
                bh[j][0] = *(const uint32_t*)(p);
                bh[j][1] = *(const uint32_t*)(p + 16);
            }
            #pragma unroll
            for (int i = 0; i < 2; ++i)
                #pragma unroll
                for (int j = 0; j < 8; ++j)
                    mma_f16(acc[i][j], ah[i], bh[j]);
        }
    }

    // ---- per-thread top-2 candidates per row-slot ----
    #pragma unroll
    for (int i = 0; i < 2; ++i) {
        #pragma unroll
        for (int h = 0; h < 2; ++h) {
            float a1 = -1.f, a2 = -1.f;
            int s1 = 0, s2 = 0;
            #pragma unroll
            for (int j = 0; j < 8; ++j) {
                #pragma unroll
                for (int cc = 0; cc < 2; ++cc) {
                    float v = acc[i][j][h * 2 + cc];
                    float a = fabsf(v);
                    int k = colbase + wn * 64 + j * 8 + tq * 2 + cc;
                    int sg = (v >= 0.f) ? k : -(k + 1);
                    if (a > a1) { a2 = a1; s2 = s1; a1 = a; s1 = sg; }
                    else if (a > a2) { a2 = a; s2 = sg; }
                }
            }
            int rl = wm * 32 + i * 16 + tg + 8 * h;
            s_cabs[0][rl][wn * 4 + tq] = a1;
            s_csig[0][rl][wn * 4 + tq] = s1;
            s_cabs[1][rl][wn * 4 + tq] = a2;
            s_csig[1][rl][wn * 4 + tq] = s2;
        }
    }
    __syncthreads();

    // ---- per-row merge 32 -> top-4, write candidates ----
    if (tid < GM) {
        float A_[4] = {-1.f, -1.f, -1.f, -1.f};
        int   S_[4] = {0, 0, 0, 0};
        #pragma unroll
        for (int t = 0; t < 16; ++t) {
            #pragma unroll
            for (int slot = 0; slot < 2; ++slot) {
                float a = s_cabs[slot][tid][t];
                int sg = s_csig[slot][tid][t];
                if (a > A_[3]) {
                    if (a > A_[0]) {
                        A_[3]=A_[2]; S_[3]=S_[2]; A_[2]=A_[1]; S_[2]=S_[1];
                        A_[1]=A_[0]; S_[1]=S_[0]; A_[0]=a; S_[0]=sg;
                    } else if (a > A_[1]) {
                        A_[3]=A_[2]; S_[3]=S_[2]; A_[2]=A_[1]; S_[2]=S_[1];
                        A_[1]=a; S_[1]=sg;
                    } else if (a > A_[2]) {
                        A_[3]=A_[2]; S_[3]=S_[2]; A_[2]=a; S_[2]=sg;
                    } else {
                        A_[3]=a; S_[3]=sg;
                    }
                }
            }
        }
        #pragma unroll
        for (int s = 0; s < 4; ++s) {
            g_pA[(cb * 4 + s) * BROWS + rowbase + tid] = A_[s];
            g_pS[(cb * 4 + s) * BROWS + rowbase + tid] = S_[s];
        }
    }
}

// ---------------- merge + exact fp32 rescore of top-4 + residual update ----------------
__global__ __launch_bounds__(256)
void lex_update(const float* __restrict__ targets, const float* __restrict__ codebook,
                float* __restrict__ out, int step, float decay) {
    __shared__ int   s_k[4][64];
    __shared__ int   s_act[64];
    __shared__ float s_coef[64];
    __shared__ int   s_kidx[64];
    const int tid = threadIdx.x;
    const int rowbase = blockIdx.x * 64;
    const float* src = (step == 0) ? targets : g_resid;

    if (tid < 64) {
        int row = rowbase + tid;
        float A_[4] = {-1.f, -1.f, -1.f, -1.f};
        int   K_[4] = {0, 0, 0, 0};
        #pragma unroll
        for (int cbi = 0; cbi < NCB; ++cbi) {
            #pragma unroll
            for (int slot = 0; slot < 4; ++slot) {
                float a = g_pA[(cbi * 4 + slot) * BROWS + row];
                int sg = g_pS[(cbi * 4 + slot) * BROWS + row];
                int k = (sg >= 0) ? sg : (-sg - 1);
                if (a > A_[3]) {
                    if (a > A_[0]) {
                        A_[3]=A_[2]; K_[3]=K_[2]; A_[2]=A_[1]; K_[2]=K_[1];
                        A_[1]=A_[0]; K_[1]=K_[0]; A_[0]=a; K_[0]=k;
                    } else if (a > A_[1]) {
                        A_[3]=A_[2]; K_[3]=K_[2]; A_[2]=A_[1]; K_[2]=K_[1];
                        A_[1]=a; K_[1]=k;
                    } else if (a > A_[2]) {
                        A_[3]=A_[2]; K_[3]=K_[2]; A_[2]=a; K_[2]=k;
                    } else {
                        A_[3]=a; K_[3]=k;
                    }
                }
            }
        }
        #pragma unroll
        for (int s = 0; s < 4; ++s) s_k[s][tid] = K_[s];
        s_act[tid] = (g_rnorm[row] >= 0.01f) && (g_tnorm[row] >= 1e-8f);
    }
    __syncthreads();

    const int m = tid >> 2, q = tid & 3;
    const int row = rowbase + m;
    const int k0 = s_k[0][m], k1 = s_k[1][m], k2 = s_k[2][m], k3 = s_k[3][m];
    {
        const float* rp = src + (size_t)row * DDIM + q * 128;
        const float* c0 = codebook + (size_t)k0 * DDIM + q * 128;
        const float* c1 = codebook + (size_t)k1 * DDIM + q * 128;
        const float* c2 = codebook + (size_t)k2 * DDIM + q * 128;
        const float* c3 = codebook + (size_t)k3 * DDIM + q * 128;
        float d0 = 0.f, d1 = 0.f, d2 = 0.f, d3 = 0.f;
        #pragma unroll 4
        for (int i = 0; i < 32; ++i) {
            float4 r4 = *(const float4*)(rp + i * 4);
            float4 v0 = *(const float4*)(c0 + i * 4);
            float4 v1 = *(const float4*)(c1 + i * 4);
            float4 v2 = *(const float4*)(c2 + i * 4);
            float4 v3 = *(const float4*)(c3 + i * 4);
            d0 += r4.x * v0.x + r4.y * v0.y + r4.z * v0.z + r4.w * v0.w;
            d1 += r4.x * v1.x + r4.y * v1.y + r4.z * v1.z + r4.w * v1.w;
            d2 += r4.x * v2.x + r4.y * v2.y + r4.z * v2.z + r4.w * v2.w;
            d3 += r4.x * v3.x + r4.y * v3.y + r4.z * v3.z + r4.w * v3.w;
        }
        d0 += __shfl_xor_sync(0xffffffffu, d0, 1); d0 += __shfl_xor_sync(0xffffffffu, d0, 2);
        d1 += __shfl_xor_sync(0xffffffffu, d1, 1); d1 += __shfl_xor_sync(0xffffffffu, d1, 2);
        d2 += __shfl_xor_sync(0xffffffffu, d2, 1); d2 += __shfl_xor_sync(0xffffffffu, d2, 2);
        d3 += __shfl_xor_sync(0xffffffffu, d3, 1); d3 += __shfl_xor_sync(0xffffffffu, d3, 2);
        if (q == 0) {
            float bD = d0; int bK = k0; float bA = fabsf(d0);
            float a1 = fabsf(d1);
            if (a1 > bA || (a1 == bA && k1 < bK)) { bA = a1; bD = d1; bK = k1; }
            float a2 = fabsf(d2);
            if (a2 > bA || (a2 == bA && k2 < bK)) { bA = a2; bD = d2; bK = k2; }
            float a3 = fabsf(d3);
            if (a3 > bA || (a3 == bA && k3 < bK)) { bA = a3; bD = d3; bK = k3; }
            int bS = (bD >= 0.f) ? bK : -(bK + 1);
            bool active = s_act[m];
            s_coef[m] = active ? ((bD >= 0.f) ? decay : -decay) : 0.f;
            s_kidx[m] = bK;
            out[(size_t)row * LSTEPS + step] = active ? (float)bS : 0.f;
            out[(size_t)BROWS * LSTEPS + (size_t)row * LSTEPS + step] = active ? 1.f : 0.f;
        }
    }
    __syncthreads();

    const bool last = (step == LSTEPS - 1);
    float* resout = out + 2 * (size_t)BROWS * LSTEPS;
    const float coef = s_coef[m];
    const int kk = s_kidx[m];
    const size_t base = (size_t)row * DDIM + q * 128;
    const size_t cbo = (size_t)kk * DDIM + q * 128;
    __half* dst = g_Ah + (size_t)row * DDIM + q * 128;
    float sum = 0.f;
    #pragma unroll 8
    for (int i = 0; i < 32; ++i) {
        float4 r4 = *(const float4*)(src + base + i * 4);
        float4 c4 = *(const float4*)(codebook + cbo + i * 4);
        float4 o;
        o.x = r4.x - coef * c4.x;
        o.y = r4.y - coef * c4.y;
        o.z = r4.z - coef * c4.z;
        o.w = r4.w - coef * c4.w;
        sum += o.x * o.x + o.y * o.y + o.z * o.z + o.w * o.w;
        *(float4*)(g_resid + base + i * 4) = o;
        __half2* d2p = (__half2*)(dst + i * 4);
        d2p[0] = __floats2half2_rn(o.x, o.y);
        d2p[1] = __floats2half2_rn(o.z, o.w);
        if (last) *(float4*)(resout + base + i * 4) = o;
    }
    sum += __shfl_xor_sync(0xffffffffu, sum, 1);
    sum += __shfl_xor_sync(0xffffffffu, sum, 2);
    if (q == 0) g_rnorm[row] = sqrtf(sum);
}

extern "C" void kernel_launch(void* const* d_in, const int* in_sizes, int n_in,
                              void* d_out, int out_size) {
    (void)n_in; (void)out_size;
    const float* targets;
    const float* codebook;
    if (in_sizes[0] == BROWS * DDIM) {
        targets  = (const float*)d_in[0];
        codebook = (const float*)d_in[1];
    } else {
        targets  = (const float*)d_in[1];
        codebook = (const float*)d_in[0];
    }
    cudaFuncSetAttribute(lex_gemm, cudaFuncAttributeMaxDynamicSharedMemorySize, SMEM_DYN);
    float* out = (float*)d_out;

    lex_prep<<<192, 256>>>(targets, codebook);
    for (int s = 0; s < LSTEPS; ++s) {
        float decay = powf(0.95f, (float)(s + 1));
        lex_gemm<<<(BROWS / GM) * NCB, GTHREADS, SMEM_DYN>>>();
        lex_update<<<BROWS / 64, 256>>>(targets, codebook, out, s, decay);
    }
}

// round 16
// speedup vs baseline: 4.3832x; 2.3893x over previous
#include <cuda_runtime.h>
#include <cuda_fp16.h>
#include <math.h>
#include <stdint.h>

#define BROWS 8192
#define DDIM  512
#define KDIM  4096
#define LSTEPS 16

#define GM 128
#define GN 256
#define NCB (KDIM / GN)        // 16 column blocks
#define NCHUNKS 16             // d-chunks of 32
#define GTHREADS 512
#define STAGES 3

#define AROWB 80
#define BROWB 80
#define ABYTES (GM * AROWB)
#define BBYTES (GN * BROWB)
#define STAGEB (ABYTES + BBYTES)
#define SMEM_DYN (STAGES * STAGEB)

#define RPB 2                  // rows per block in lex_step

// ---------------- device state ----------------
__device__ __align__(128) float g_resid[BROWS * DDIM];
__device__ __align__(128) __half g_Ah[BROWS * DDIM];
__device__ __align__(128) __half g_Bh[KDIM * DDIM];
__device__ __align__(128) float g_scores[(size_t)BROWS * KDIM];  // 128 MB
__device__ __align__(128) float g_G[(size_t)KDIM * KDIM];        // 64 MB
__device__ float g_rnorm[BROWS];
__device__ float g_tnorm[BROWS];
__device__ float g_pA[4 * NCB * BROWS];
__device__ int   g_pS[4 * NCB * BROWS];
__device__ int   g_kprev[BROWS];
__device__ float g_coef[BROWS];

// ---------------- helpers ----------------
__device__ __forceinline__ uint32_t smem_u32(const void* p) {
    uint32_t a;
    asm("{ .reg .u64 t; cvta.to.shared.u64 t, %1; cvt.u32.u64 %0, t; }" : "=r"(a) : "l"(p));
    return a;
}
__device__ __forceinline__ void cpasync16(uint32_t dst, const void* src) {
    asm volatile("cp.async.cg.shared.global [%0], [%1], 16;" :: "r"(dst), "l"(src));
}
#define CP_COMMIT() asm volatile("cp.async.commit_group;" ::: "memory")

__device__ __forceinline__ void mma_f16(float* d, const uint32_t* a, const uint32_t* b) {
    asm volatile(
        "mma.sync.aligned.m16n8k16.row.col.f32.f16.f16.f32 "
        "{%0,%1,%2,%3}, {%4,%5,%6,%7}, {%8,%9}, {%0,%1,%2,%3};"
        : "+f"(d[0]), "+f"(d[1]), "+f"(d[2]), "+f"(d[3])
        : "r"(a[0]), "r"(a[1]), "r"(a[2]), "r"(a[3]), "r"(b[0]), "r"(b[1]));
}

// ---------------- prep: A -> fp16, B -> fp16, norms ----------------
__global__ __launch_bounds__(256)
void lex_prep(const float* __restrict__ targets, const float* __restrict__ codebook) {
    const int tid = threadIdx.x;
    const int m = tid >> 2, q = tid & 3;
    if (blockIdx.x < 128) {
        int row = blockIdx.x * 64 + m;
        const float* src = targets + (size_t)row * DDIM + q * 128;
        __half* dst = g_Ah + (size_t)row * DDIM + q * 128;
        float sum = 0.f;
        #pragma unroll 8
        for (int i = 0; i < 128; ++i) {
            float v = src[i];
            sum += v * v;
            dst[i] = __float2half(v);
        }
        sum += __shfl_xor_sync(0xffffffffu, sum, 1);
        sum += __shfl_xor_sync(0xffffffffu, sum, 2);
        if (q == 0) { float n = sqrtf(sum); g_rnorm[row] = n; g_tnorm[row] = n; }
    } else {
        int row = (blockIdx.x - 128) * 64 + m;
        const float* src = codebook + (size_t)row * DDIM + q * 128;
        __half* dst = g_Bh + (size_t)row * DDIM + q * 128;
        #pragma unroll 8
        for (int i = 0; i < 128; ++i) {
            dst[i] = __float2half(src[i]);
        }
    }
}

// ---------------- shared mainloop macro-free: staged fp16 GEMM body ----------------
// (used by lex_gemm and lex_gram with different sources/epilogues)

// ---------------- GEMM (step 0) + score dump + top-4 candidates ----------------
__global__ __launch_bounds__(GTHREADS, 1)
void lex_gemm() {
    extern __shared__ char dsm[];
    __shared__ float s_cabs[2][GM][17];
    __shared__ int   s_csig[2][GM][17];

    const int tid = threadIdx.x;
    const int wid = tid >> 5;
    const int lane = tid & 31;
    const int tg = lane >> 2;
    const int tq = lane & 3;
    const int wm = wid >> 2;
    const int wn = wid & 3;
    const int rowblock = blockIdx.x >> 4;
    const int cb = blockIdx.x & 15;
    const int rowbase = rowblock * GM;
    const int colbase = cb * GN;
    const uint32_t sbase = smem_u32(dsm);

    auto issue = [&](int c) {
        const int dbase = c * 32;
        const uint32_t base = sbase + (uint32_t)(c % STAGES) * STAGEB;
        {
            int r = tid >> 2, c16 = tid & 3;
            cpasync16(base + (uint32_t)(r * AROWB + c16 * 16),
                      g_Ah + (size_t)(rowbase + r) * DDIM + dbase + c16 * 8);
        }
        #pragma unroll
        for (int i = 0; i < 2; ++i) {
            int idx = tid + i * GTHREADS;
            int n = idx >> 2, c16 = idx & 3;
            cpasync16(base + ABYTES + (uint32_t)(n * BROWB + c16 * 16),
                      g_Bh + (size_t)(colbase + n) * DDIM + dbase + c16 * 8);
        }
        CP_COMMIT();
    };

    float acc[2][8][4];
    #pragma unroll
    for (int i = 0; i < 2; ++i)
        #pragma unroll
        for (int j = 0; j < 8; ++j)
            #pragma unroll
            for (int r = 0; r < 4; ++r) acc[i][j][r] = 0.f;

    issue(0); issue(1);

    for (int c = 0; c < NCHUNKS; ++c) {
        asm volatile("cp.async.wait_group 1;" ::: "memory");
        __syncthreads();
        if (c + 2 < NCHUNKS) issue(c + 2);
        else CP_COMMIT();

        const char* As = dsm + (size_t)(c % STAGES) * STAGEB;
        const char* Bs = As + ABYTES;

        #pragma unroll
        for (int ks = 0; ks < 2; ++ks) {
            const int koff = ks * 32;
            uint32_t ah[2][4];
            #pragma unroll
            for (int i = 0; i < 2; ++i) {
                const char* p = As + (wm * 32 + i * 16 + tg) * AROWB + koff + tq * 4;
                ah[i][0] = *(const uint32_t*)(p);
                ah[i][1] = *(const uint32_t*)(p + 8 * AROWB);
                ah[i][2] = *(const uint32_t*)(p + 16);
                ah[i][3] = *(const uint32_t*)(p + 8 * AROWB + 16);
            }
            uint32_t bh[8][2];
            #pragma unroll
            for (int j = 0; j < 8; ++j) {
                const char* p = Bs + (wn * 64 + j * 8 + tg) * BROWB + koff + tq * 4;
                bh[j][0] = *(const uint32_t*)(p);
                bh[j][1] = *(const uint32_t*)(p + 16);
            }
            #pragma unroll
            for (int i = 0; i < 2; ++i)
                #pragma unroll
                for (int j = 0; j < 8; ++j)
                    mma_f16(acc[i][j], ah[i], bh[j]);
        }
    }

    // ---- dump scores (for incremental steps 1..15) ----
    #pragma unroll
    for (int i = 0; i < 2; ++i)
        #pragma unroll
        for (int h = 0; h < 2; ++h) {
            int rg = rowbase + wm * 32 + i * 16 + tg + 8 * h;
            float* sp = g_scores + (size_t)rg * KDIM + colbase + wn * 64 + tq * 2;
            #pragma unroll
            for (int j = 0; j < 8; ++j)
                *(float2*)(sp + j * 8) = make_float2(acc[i][j][h * 2], acc[i][j][h * 2 + 1]);
        }

    // ---- per-thread top-2 candidates per row-slot ----
    #pragma unroll
    for (int i = 0; i < 2; ++i) {
        #pragma unroll
        for (int h = 0; h < 2; ++h) {
            float a1 = -1.f, a2 = -1.f;
            int s1 = 0, s2 = 0;
            #pragma unroll
            for (int j = 0; j < 8; ++j) {
                #pragma unroll
                for (int cc = 0; cc < 2; ++cc) {
                    float v = acc[i][j][h * 2 + cc];
                    float a = fabsf(v);
                    int k = colbase + wn * 64 + j * 8 + tq * 2 + cc;
                    int sg = (v >= 0.f) ? k : -(k + 1);
                    if (a > a1) { a2 = a1; s2 = s1; a1 = a; s1 = sg; }
                    else if (a > a2) { a2 = a; s2 = sg; }
                }
            }
            int rl = wm * 32 + i * 16 + tg + 8 * h;
            s_cabs[0][rl][wn * 4 + tq] = a1;
            s_csig[0][rl][wn * 4 + tq] = s1;
            s_cabs[1][rl][wn * 4 + tq] = a2;
            s_csig[1][rl][wn * 4 + tq] = s2;
        }
    }
    __syncthreads();

    if (tid < GM) {
        float A_[4] = {-1.f, -1.f, -1.f, -1.f};
        int   S_[4] = {0, 0, 0, 0};
        #pragma unroll
        for (int t = 0; t < 16; ++t) {
            #pragma unroll
            for (int slot = 0; slot < 2; ++slot) {
                float a = s_cabs[slot][tid][t];
                int sg = s_csig[slot][tid][t];
                if (a > A_[3]) {
                    if (a > A_[0]) {
                        A_[3]=A_[2]; S_[3]=S_[2]; A_[2]=A_[1]; S_[2]=S_[1];
                        A_[1]=A_[0]; S_[1]=S_[0]; A_[0]=a; S_[0]=sg;
                    } else if (a > A_[1]) {
                        A_[3]=A_[2]; S_[3]=S_[2]; A_[2]=A_[1]; S_[2]=S_[1];
                        A_[1]=a; S_[1]=sg;
                    } else if (a > A_[2]) {
                        A_[3]=A_[2]; S_[3]=S_[2]; A_[2]=a; S_[2]=sg;
                    } else {
                        A_[3]=a; S_[3]=sg;
                    }
                }
            }
        }
        #pragma unroll
        for (int s = 0; s < 4; ++s) {
            g_pA[(cb * 4 + s) * BROWS + rowbase + tid] = A_[s];
            g_pS[(cb * 4 + s) * BROWS + rowbase + tid] = S_[s];
        }
    }
}

// ---------------- Gram: G = C * C^T (fp16 mma, fp32 out), one-time ----------------
__global__ __launch_bounds__(GTHREADS, 1)
void lex_gram() {
    extern __shared__ char dsm[];
    const int tid = threadIdx.x;
    const int wid = tid >> 5;
    const int lane = tid & 31;
    const int tg = lane >> 2;
    const int tq = lane & 3;
    const int wm = wid >> 2;
    const int wn = wid & 3;
    const int rowblock = blockIdx.x >> 4;     // 0..31
    const int cb = blockIdx.x & 15;           // 0..15
    const int rowbase = rowblock * GM;        // over codebook rows
    const int colbase = cb * GN;              // over codebook rows
    const uint32_t sbase = smem_u32(dsm);

    auto issue = [&](int c) {
        const int dbase = c * 32;
        const uint32_t base = sbase + (uint32_t)(c % STAGES) * STAGEB;
        {
            int r = tid >> 2, c16 = tid & 3;
            cpasync16(base + (uint32_t)(r * AROWB + c16 * 16),
                      g_Bh + (size_t)(rowbase + r) * DDIM + dbase + c16 * 8);
        }
        #pragma unroll
        for (int i = 0; i < 2; ++i) {
            int idx = tid + i * GTHREADS;
            int n = idx >> 2, c16 = idx & 3;
            cpasync16(base + ABYTES + (uint32_t)(n * BROWB + c16 * 16),
                      g_Bh + (size_t)(colbase + n) * DDIM + dbase + c16 * 8);
        }
        CP_COMMIT();
    };

    float acc[2][8][4];
    #pragma unroll
    for (int i = 0; i < 2; ++i)
        #pragma unroll
        for (int j = 0; j < 8; ++j)
            #pragma unroll
            for (int r = 0; r < 4; ++r) acc[i][j][r] = 0.f;

    issue(0); issue(1);

    for (int c = 0; c < NCHUNKS; ++c) {
        asm volatile("cp.async.wait_group 1;" ::: "memory");
        __syncthreads();
        if (c + 2 < NCHUNKS) issue(c + 2);
        else CP_COMMIT();

        const char* As = dsm + (size_t)(c % STAGES) * STAGEB;
        const char* Bs = As + ABYTES;

        #pragma unroll
        for (int ks = 0; ks < 2; ++ks) {
            const int koff = ks * 32;
            uint32_t ah[2][4];
            #pragma unroll
            for (int i = 0; i < 2; ++i) {
                const char* p = As + (wm * 32 + i * 16 + tg) * AROWB + koff + tq * 4;
                ah[i][0] = *(const uint32_t*)(p);
                ah[i][1] = *(const uint32_t*)(p + 8 * AROWB);
                ah[i][2] = *(const uint32_t*)(p + 16);
                ah[i][3] = *(const uint32_t*)(p + 8 * AROWB + 16);
            }
            uint32_t bh[8][2];
            #pragma unroll
            for (int j = 0; j < 8; ++j) {
                const char* p = Bs + (wn * 64 + j * 8 + tg) * BROWB + koff + tq * 4;
                bh[j][0] = *(const uint32_t*)(p);
                bh[j][1] = *(const uint32_t*)(p + 16);
            }
            #pragma unroll
            for (int i = 0; i < 2; ++i)
                #pragma unroll
                for (int j = 0; j < 8; ++j)
                    mma_f16(acc[i][j], ah[i], bh[j]);
        }
    }

    // write G tile
    #pragma unroll
    for (int i = 0; i < 2; ++i)
        #pragma unroll
        for (int h = 0; h < 2; ++h) {
            int rg = rowbase + wm * 32 + i * 16 + tg + 8 * h;
            float* gp = g_G + (size_t)rg * KDIM + colbase + wn * 64 + tq * 2;
            #pragma unroll
            for (int j = 0; j < 8; ++j)
                *(float2*)(gp + j * 8) = make_float2(acc[i][j][h * 2], acc[i][j][h * 2 + 1]);
        }
}

// ---------------- step 0: merge + exact rescore + residual update ----------------
__global__ __launch_bounds__(256)
void lex_update(const float* __restrict__ targets, const float* __restrict__ codebook,
                float* __restrict__ out, int step, float decay) {
    __shared__ int   s_k[4][64];
    __shared__ int   s_act[64];
    __shared__ float s_coef[64];
    __shared__ int   s_kidx[64];
    const int tid = threadIdx.x;
    const int rowbase = blockIdx.x * 64;
    const float* src = targets;    // step 0 only

    if (tid < 64) {
        int row = rowbase + tid;
        float A_[4] = {-1.f, -1.f, -1.f, -1.f};
        int   K_[4] = {0, 0, 0, 0};
        #pragma unroll
        for (int cbi = 0; cbi < NCB; ++cbi) {
            #pragma unroll
            for (int slot = 0; slot < 4; ++slot) {
                float a = g_pA[(cbi * 4 + slot) * BROWS + row];
                int sg = g_pS[(cbi * 4 + slot) * BROWS + row];
                int k = (sg >= 0) ? sg : (-sg - 1);
                if (a > A_[3]) {
                    if (a > A_[0]) {
                        A_[3]=A_[2]; K_[3]=K_[2]; A_[2]=A_[1]; K_[2]=K_[1];
                        A_[1]=A_[0]; K_[1]=K_[0]; A_[0]=a; K_[0]=k;
                    } else if (a > A_[1]) {
                        A_[3]=A_[2]; K_[3]=K_[2]; A_[2]=A_[1]; K_[2]=K_[1];
                        A_[1]=a; K_[1]=k;
                    } else if (a > A_[2]) {
                        A_[3]=A_[2]; K_[3]=K_[2]; A_[2]=a; K_[2]=k;
                    } else {
                        A_[3]=a; K_[3]=k;
                    }
                }
            }
        }
        #pragma unroll
        for (int s = 0; s < 4; ++s) s_k[s][tid] = K_[s];
        s_act[tid] = (g_rnorm[row] >= 0.01f) && (g_tnorm[row] >= 1e-8f);
    }
    __syncthreads();

    const int m = tid >> 2, q = tid & 3;
    const int row = rowbase + m;
    const int k0 = s_k[0][m], k1 = s_k[1][m], k2 = s_k[2][m], k3 = s_k[3][m];
    {
        const float* rp = src + (size_t)row * DDIM + q * 128;
        const float* c0 = codebook + (size_t)k0 * DDIM + q * 128;
        const float* c1 = codebook + (size_t)k1 * DDIM + q * 128;
        const float* c2 = codebook + (size_t)k2 * DDIM + q * 128;
        const float* c3 = codebook + (size_t)k3 * DDIM + q * 128;
        float d0 = 0.f, d1 = 0.f, d2 = 0.f, d3 = 0.f;
        #pragma unroll 4
        for (int i = 0; i < 32; ++i) {
            float4 r4 = *(const float4*)(rp + i * 4);
            float4 v0 = *(const float4*)(c0 + i * 4);
            float4 v1 = *(const float4*)(c1 + i * 4);
            float4 v2 = *(const float4*)(c2 + i * 4);
            float4 v3 = *(const float4*)(c3 + i * 4);
            d0 += r4.x * v0.x + r4.y * v0.y + r4.z * v0.z + r4.w * v0.w;
            d1 += r4.x * v1.x + r4.y * v1.y + r4.z * v1.z + r4.w * v1.w;
            d2 += r4.x * v2.x + r4.y * v2.y + r4.z * v2.z + r4.w * v2.w;
            d3 += r4.x * v3.x + r4.y * v3.y + r4.z * v3.z + r4.w * v3.w;
        }
        d0 += __shfl_xor_sync(0xffffffffu, d0, 1); d0 += __shfl_xor_sync(0xffffffffu, d0, 2);
        d1 += __shfl_xor_sync(0xffffffffu, d1, 1); d1 += __shfl_xor_sync(0xffffffffu, d1, 2);
        d2 += __shfl_xor_sync(0xffffffffu, d2, 1); d2 += __shfl_xor_sync(0xffffffffu, d2, 2);
        d3 += __shfl_xor_sync(0xffffffffu, d3, 1); d3 += __shfl_xor_sync(0xffffffffu, d3, 2);
        if (q == 0) {
            float bD = d0; int bK = k0; float bA = fabsf(d0);
            float a1 = fabsf(d1);
            if (a1 > bA || (a1 == bA && k1 < bK)) { bA = a1; bD = d1; bK = k1; }
            float a2 = fabsf(d2);
            if (a2 > bA || (a2 == bA && k2 < bK)) { bA = a2; bD = d2; bK = k2; }
            float a3 = fabsf(d3);
            if (a3 > bA || (a3 == bA && k3 < bK)) { bA = a3; bD = d3; bK = k3; }
            int bS = (bD >= 0.f) ? bK : -(bK + 1);
            bool active = s_act[m];
            float coef = active ? ((bD >= 0.f) ? decay : -decay) : 0.f;
            s_coef[m] = coef;
            s_kidx[m] = bK;
            g_kprev[row] = bK;
            g_coef[row] = coef;
            out[(size_t)row * LSTEPS + step] = active ? (float)bS : 0.f;
            out[(size_t)BROWS * LSTEPS + (size_t)row * LSTEPS + step] = active ? 1.f : 0.f;
        }
    }
    __syncthreads();

    const float coef = s_coef[m];
    const int kk = s_kidx[m];
    const size_t base = (size_t)row * DDIM + q * 128;
    const size_t cbo = (size_t)kk * DDIM + q * 128;
    float sum = 0.f;
    #pragma unroll 8
    for (int i = 0; i < 32; ++i) {
        float4 r4 = *(const float4*)(src + base + i * 4);
        float4 c4 = *(const float4*)(codebook + cbo + i * 4);
        float4 o;
        o.x = r4.x - coef * c4.x;
        o.y = r4.y - coef * c4.y;
        o.z = r4.z - coef * c4.z;
        o.w = r4.w - coef * c4.w;
        sum += o.x * o.x + o.y * o.y + o.z * o.z + o.w * o.w;
        *(float4*)(g_resid + base + i * 4) = o;
    }
    sum += __shfl_xor_sync(0xffffffffu, sum, 1);
    sum += __shfl_xor_sync(0xffffffffu, sum, 2);
    if (q == 0) g_rnorm[row] = sqrtf(sum);
}

// ---------------- steps 1..15: incremental scores + nominate + rescore + update ----------------
__global__ __launch_bounds__(256)
void lex_step(const float* __restrict__ codebook, float* __restrict__ out,
              int step, float decay) {
    __shared__ float s_ca[RPB][8];
    __shared__ int   s_ck[RPB][8];
    __shared__ int   s_k4[RPB][4];
    __shared__ float s_d[RPB][4];
    __shared__ float s_nrm[RPB][4];
    __shared__ float s_coef[RPB];
    __shared__ int   s_kid[RPB];

    const int tid = threadIdx.x;
    const int r = tid >> 7;            // 0..1
    const int t = tid & 127;
    const int w = t >> 5;
    const int lane = t & 31;
    const int row = blockIdx.x * RPB + r;

    const float coefp = g_coef[row];
    const int   kprev = g_kprev[row];
    float* sc = g_scores + (size_t)row * KDIM;
    const float* grow = g_G + (size_t)kprev * KDIM;

    // phase 1: score update + per-thread top-2 (|score|), lowest-k tie-break via scan order
    float a1 = -1.f, a2 = -1.f; int k1 = 0, k2 = 0;
    #pragma unroll
    for (int i = 0; i < 8; ++i) {
        int k4 = (t + 128 * i) * 4;
        float4 g4 = *(const float4*)(grow + k4);
        float4 s4 = *(const float4*)(sc + k4);
        s4.x -= coefp * g4.x;
        s4.y -= coefp * g4.y;
        s4.z -= coefp * g4.z;
        s4.w -= coefp * g4.w;
        *(float4*)(sc + k4) = s4;
        float av;
        av = fabsf(s4.x); if (av > a1) { a2=a1;k2=k1; a1=av;k1=k4;   } else if (av > a2) { a2=av;k2=k4;   }
        av = fabsf(s4.y); if (av > a1) { a2=a1;k2=k1; a1=av;k1=k4+1; } else if (av > a2) { a2=av;k2=k4+1; }
        av = fabsf(s4.z); if (av > a1) { a2=a1;k2=k1; a1=av;k1=k4+2; } else if (av > a2) { a2=av;k2=k4+2; }
        av = fabsf(s4.w); if (av > a1) { a2=a1;k2=k1; a1=av;k1=k4+3; } else if (av > a2) { a2=av;k2=k4+3; }
    }
    // warp merge of top-2 lists (tie -> lower k)
    #pragma unroll
    for (int off = 1; off < 32; off <<= 1) {
        float b1 = __shfl_xor_sync(0xffffffffu, a1, off);
        int   j1 = __shfl_xor_sync(0xffffffffu, k1, off);
        float b2 = __shfl_xor_sync(0xffffffffu, a2, off);
        int   j2 = __shfl_xor_sync(0xffffffffu, k2, off);
        bool fA = (a1 > b1) || (a1 == b1 && k1 < j1);
        float n1  = fA ? a1 : b1;  int n1k  = fA ? k1 : j1;
        float c2  = fA ? b1 : a1;  int c2k  = fA ? j1 : k1;
        float alt = fA ? a2 : b2;  int altk = fA ? k2 : j2;
        bool s2A = (c2 > alt) || (c2 == alt && c2k < altk);
        a1 = n1; k1 = n1k;
        a2 = s2A ? c2 : alt; k2 = s2A ? c2k : altk;
    }
    if (lane == 0) {
        s_ca[r][w * 2]     = a1; s_ck[r][w * 2]     = k1;
        s_ca[r][w * 2 + 1] = a2; s_ck[r][w * 2 + 1] = k2;
    }
    __syncthreads();

    // per-row merge 8 -> top-4
    if (t == 0) {
        float A_[4] = {-1.f, -1.f, -1.f, -1.f};
        int   K_[4] = {0, 0, 0, 0};
        #pragma unroll
        for (int e = 0; e < 8; ++e) {
            float a = s_ca[r][e]; int k = s_ck[r][e];
            if (a > A_[3] || (a == A_[3] && k < K_[3])) {
                if (a > A_[0] || (a == A_[0] && k < K_[0])) {
                    A_[3]=A_[2]; K_[3]=K_[2]; A_[2]=A_[1]; K_[2]=K_[1];
                    A_[1]=A_[0]; K_[1]=K_[0]; A_[0]=a; K_[0]=k;
                } else if (a > A_[1] || (a == A_[1] && k < K_[1])) {
                    A_[3]=A_[2]; K_[3]=K_[2]; A_[2]=A_[1]; K_[2]=K_[1];
                    A_[1]=a; K_[1]=k;
                } else if (a > A_[2] || (a == A_[2] && k < K_[2])) {
                    A_[3]=A_[2]; K_[3]=K_[2]; A_[2]=a; K_[2]=k;
                } else {
                    A_[3]=a; K_[3]=k;
                }
            }
        }
        #pragma unroll
        for (int s = 0; s < 4; ++s) s_k4[r][s] = K_[s];
    }
    __syncthreads();

    // phase 2: exact fp32 rescore (warp w -> candidate w)
    {
        int kc = s_k4[r][w];
        const float* rp = g_resid + (size_t)row * DDIM;
        const float* cp = codebook + (size_t)kc * DDIM;
        float d = 0.f;
        #pragma unroll
        for (int ii = 0; ii < 4; ++ii) {
            int idx = (lane + 32 * ii) * 4;
            float4 r4 = *(const float4*)(rp + idx);
            float4 c4 = *(const float4*)(cp + idx);
            d += r4.x * c4.x + r4.y * c4.y + r4.z * c4.z + r4.w * c4.w;
        }
        #pragma unroll
        for (int off = 16; off; off >>= 1) d += __shfl_xor_sync(0xffffffffu, d, off);
        if (lane == 0) s_d[r][w] = d;
    }
    __syncthreads();

    if (t == 0) {
        float bD = s_d[r][0]; int bK = s_k4[r][0]; float bA = fabsf(bD);
        #pragma unroll
        for (int c = 1; c < 4; ++c) {
            float dd = s_d[r][c]; float aa = fabsf(dd); int kk2 = s_k4[r][c];
            if (aa > bA || (aa == bA && kk2 < bK)) { bA = aa; bD = dd; bK = kk2; }
        }
        bool active = (g_rnorm[row] >= 0.01f) && (g_tnorm[row] >= 1e-8f);
        float coef = active ? ((bD >= 0.f) ? decay : -decay) : 0.f;
        int bS = (bD >= 0.f) ? bK : -(bK + 1);
        s_coef[r] = coef; s_kid[r] = bK;
        g_coef[row] = coef; g_kprev[row] = bK;
        out[(size_t)row * LSTEPS + step] = active ? (float)bS : 0.f;
        out[(size_t)BROWS * LSTEPS + (size_t)row * LSTEPS + step] = active ? 1.f : 0.f;
    }
    __syncthreads();

    // phase 3: residual update + norm
    {
        const float coef = s_coef[r];
        const int kk = s_kid[r];
        float4 r4 = *(const float4*)(g_resid + (size_t)row * DDIM + t * 4);
        float4 c4 = *(const float4*)(codebook + (size_t)kk * DDIM + t * 4);
        float4 o;
        o.x = r4.x - coef * c4.x;
        o.y = r4.y - coef * c4.y;
        o.z = r4.z - coef * c4.z;
        o.w = r4.w - coef * c4.w;
        *(float4*)(g_resid + (size_t)row * DDIM + t * 4) = o;
        if (step == LSTEPS - 1)
            *(float4*)(out + 2 * (size_t)BROWS * LSTEPS + (size_t)row * DDIM + t * 4) = o;
        float s = o.x * o.x + o.y * o.y + o.z * o.z + o.w * o.w;
        #pragma unroll
        for (int off = 16; off; off >>= 1) s += __shfl_xor_sync(0xffffffffu, s, off);
        if (lane == 0) s_nrm[r][w] = s;
    }
    __syncthreads();
    if (t == 0)
        g_rnorm[row] = sqrtf(s_nrm[r][0] + s_nrm[r][1] + s_nrm[r][2] + s_nrm[r][3]);
}

extern "C" void kernel_launch(void* const* d_in, const int* in_sizes, int n_in,
                              void* d_out, int out_size) {
    (void)n_in; (void)out_size;
    const float* targets;
    const float* codebook;
    if (in_sizes[0] == BROWS * DDIM) {
        targets  = (const float*)d_in[0];
        codebook = (const float*)d_in[1];
    } else {
        targets  = (const float*)d_in[1];
        codebook = (const float*)d_in[0];
    }
    cudaFuncSetAttribute(lex_gemm, cudaFuncAttributeMaxDynamicSharedMemorySize, SMEM_DYN);
    cudaFuncSetAttribute(lex_gram, cudaFuncAttributeMaxDynamicSharedMemorySize, SMEM_DYN);
    float* out = (float*)d_out;

    lex_prep<<<192, 256>>>(targets, codebook);
    lex_gram<<<(KDIM / GM) * (KDIM / GN), GTHREADS, SMEM_DYN>>>();
    lex_gemm<<<(BROWS / GM) * NCB, GTHREADS, SMEM_DYN>>>();
    lex_update<<<BROWS / 64, 256>>>(targets, codebook, out, 0, 0.95f);
    for (int s = 1; s < LSTEPS; ++s) {
        float decay = powf(0.95f, (float)(s + 1));
        lex_step<<<BROWS / RPB, 256>>>(codebook, out, s, decay);
    }
}

// round 17
// speedup vs baseline: 7.2906x; 1.6633x over previous
#include <cuda_runtime.h>
#include <cuda_fp16.h>
#include <math.h>
#include <stdint.h>

#define BROWS 8192
#define DDIM  512
#define KDIM  4096
#define LSTEPS 16

#define GM 128
#define GN 256
#define NCB (KDIM / GN)        // 16 column blocks
#define NCHUNKS 16             // d-chunks of 32
#define GTHREADS 512
#define STAGES 3

#define AROWB 80
#define BROWB 80
#define ABYTES (GM * AROWB)
#define BBYTES (GN * BROWB)
#define STAGEB (ABYTES + BBYTES)
#define SMEM_DYN (STAGES * STAGEB)

#define RPB 2                  // rows per block in lex_steps

// ---------------- device state ----------------
__device__ __align__(128) float g_resid[BROWS * DDIM];
__device__ __align__(128) __half g_Ah[BROWS * DDIM];
__device__ __align__(128) __half g_Bh[KDIM * DDIM];
__device__ __align__(128) float g_scores[(size_t)BROWS * KDIM];  // 128 MB
__device__ __align__(128) float g_G[(size_t)KDIM * KDIM];        // 64 MB
__device__ float g_rnorm[BROWS];
__device__ float g_tnorm[BROWS];
__device__ float g_pA[4 * NCB * BROWS];
__device__ int   g_pS[4 * NCB * BROWS];
__device__ int   g_kprev[BROWS];
__device__ float g_coef[BROWS];

// ---------------- helpers ----------------
__device__ __forceinline__ uint32_t smem_u32(const void* p) {
    uint32_t a;
    asm("{ .reg .u64 t; cvta.to.shared.u64 t, %1; cvt.u32.u64 %0, t; }" : "=r"(a) : "l"(p));
    return a;
}
__device__ __forceinline__ void cpasync16(uint32_t dst, const void* src) {
    asm volatile("cp.async.cg.shared.global [%0], [%1], 16;" :: "r"(dst), "l"(src));
}
#define CP_COMMIT() asm volatile("cp.async.commit_group;" ::: "memory")

__device__ __forceinline__ void mma_f16(float* d, const uint32_t* a, const uint32_t* b) {
    asm volatile(
        "mma.sync.aligned.m16n8k16.row.col.f32.f16.f16.f32 "
        "{%0,%1,%2,%3}, {%4,%5,%6,%7}, {%8,%9}, {%0,%1,%2,%3};"
        : "+f"(d[0]), "+f"(d[1]), "+f"(d[2]), "+f"(d[3])
        : "r"(a[0]), "r"(a[1]), "r"(a[2]), "r"(a[3]), "r"(b[0]), "r"(b[1]));
}

// ---------------- prep: A -> fp16, B -> fp16, norms ----------------
__global__ __launch_bounds__(256)
void lex_prep(const float* __restrict__ targets, const float* __restrict__ codebook) {
    const int tid = threadIdx.x;
    const int m = tid >> 2, q = tid & 3;
    if (blockIdx.x < 128) {
        int row = blockIdx.x * 64 + m;
        const float* src = targets + (size_t)row * DDIM + q * 128;
        __half* dst = g_Ah + (size_t)row * DDIM + q * 128;
        float sum = 0.f;
        #pragma unroll 8
        for (int i = 0; i < 128; ++i) {
            float v = src[i];
            sum += v * v;
            dst[i] = __float2half(v);
        }
        sum += __shfl_xor_sync(0xffffffffu, sum, 1);
        sum += __shfl_xor_sync(0xffffffffu, sum, 2);
        if (q == 0) { float n = sqrtf(sum); g_rnorm[row] = n; g_tnorm[row] = n; }
    } else {
        int row = (blockIdx.x - 128) * 64 + m;
        const float* src = codebook + (size_t)row * DDIM + q * 128;
        __half* dst = g_Bh + (size_t)row * DDIM + q * 128;
        #pragma unroll 8
        for (int i = 0; i < 128; ++i) {
            dst[i] = __float2half(src[i]);
        }
    }
}

// ---------------- GEMM (step 0) + score dump + top-4 candidates ----------------
__global__ __launch_bounds__(GTHREADS, 1)
void lex_gemm() {
    extern __shared__ char dsm[];
    __shared__ float s_cabs[2][GM][17];
    __shared__ int   s_csig[2][GM][17];

    const int tid = threadIdx.x;
    const int wid = tid >> 5;
    const int lane = tid & 31;
    const int tg = lane >> 2;
    const int tq = lane & 3;
    const int wm = wid >> 2;
    const int wn = wid & 3;
    const int rowblock = blockIdx.x >> 4;
    const int cb = blockIdx.x & 15;
    const int rowbase = rowblock * GM;
    const int colbase = cb * GN;
    const uint32_t sbase = smem_u32(dsm);

    auto issue = [&](int c) {
        const int dbase = c * 32;
        const uint32_t base = sbase + (uint32_t)(c % STAGES) * STAGEB;
        {
            int r = tid >> 2, c16 = tid & 3;
            cpasync16(base + (uint32_t)(r * AROWB + c16 * 16),
                      g_Ah + (size_t)(rowbase + r) * DDIM + dbase + c16 * 8);
        }
        #pragma unroll
        for (int i = 0; i < 2; ++i) {
            int idx = tid + i * GTHREADS;
            int n = idx >> 2, c16 = idx & 3;
            cpasync16(base + ABYTES + (uint32_t)(n * BROWB + c16 * 16),
                      g_Bh + (size_t)(colbase + n) * DDIM + dbase + c16 * 8);
        }
        CP_COMMIT();
    };

    float acc[2][8][4];
    #pragma unroll
    for (int i = 0; i < 2; ++i)
        #pragma unroll
        for (int j = 0; j < 8; ++j)
            #pragma unroll
            for (int r = 0; r < 4; ++r) acc[i][j][r] = 0.f;

    issue(0); issue(1);

    for (int c = 0; c < NCHUNKS; ++c) {
        asm volatile("cp.async.wait_group 1;" ::: "memory");
        __syncthreads();
        if (c + 2 < NCHUNKS) issue(c + 2);
        else CP_COMMIT();

        const char* As = dsm + (size_t)(c % STAGES) * STAGEB;
        const char* Bs = As + ABYTES;

        #pragma unroll
        for (int ks = 0; ks < 2; ++ks) {
            const int koff = ks * 32;
            uint32_t ah[2][4];
            #pragma unroll
            for (int i = 0; i < 2; ++i) {
                const char* p = As + (wm * 32 + i * 16 + tg) * AROWB + koff + tq * 4;
                ah[i][0] = *(const uint32_t*)(p);
                ah[i][1] = *(const uint32_t*)(p + 8 * AROWB);
                ah[i][2] = *(const uint32_t*)(p + 16);
                ah[i][3] = *(const uint32_t*)(p + 8 * AROWB + 16);
            }
            uint32_t bh[8][2];
            #pragma unroll
            for (int j = 0; j < 8; ++j) {
                const char* p = Bs + (wn * 64 + j * 8 + tg) * BROWB + koff + tq * 4;
                bh[j][0] = *(const uint32_t*)(p);
                bh[j][1] = *(const uint32_t*)(p + 16);
            }
            #pragma unroll
            for (int i = 0; i < 2; ++i)
                #pragma unroll
                for (int j = 0; j < 8; ++j)
                    mma_f16(acc[i][j], ah[i], bh[j]);
        }
    }

    // ---- dump scores (for incremental steps 1..15) ----
    #pragma unroll
    for (int i = 0; i < 2; ++i)
        #pragma unroll
        for (int h = 0; h < 2; ++h) {
            int rg = rowbase + wm * 32 + i * 16 + tg + 8 * h;
            float* sp = g_scores + (size_t)rg * KDIM + colbase + wn * 64 + tq * 2;
            #pragma unroll
            for (int j = 0; j < 8; ++j)
                *(float2*)(sp + j * 8) = make_float2(acc[i][j][h * 2], acc[i][j][h * 2 + 1]);
        }

    // ---- per-thread top-2 candidates per row-slot ----
    #pragma unroll
    for (int i = 0; i < 2; ++i) {
        #pragma unroll
        for (int h = 0; h < 2; ++h) {
            float a1 = -1.f, a2 = -1.f;
            int s1 = 0, s2 = 0;
            #pragma unroll
            for (int j = 0; j < 8; ++j) {
                #pragma unroll
                for (int cc = 0; cc < 2; ++cc) {
                    float v = acc[i][j][h * 2 + cc];
                    float a = fabsf(v);
                    int k = colbase + wn * 64 + j * 8 + tq * 2 + cc;
                    int sg = (v >= 0.f) ? k : -(k + 1);
                    if (a > a1) { a2 = a1; s2 = s1; a1 = a; s1 = sg; }
                    else if (a > a2) { a2 = a; s2 = sg; }
                }
            }
            int rl = wm * 32 + i * 16 + tg + 8 * h;
            s_cabs[0][rl][wn * 4 + tq] = a1;
            s_csig[0][rl][wn * 4 + tq] = s1;
            s_cabs[1][rl][wn * 4 + tq] = a2;
            s_csig[1][rl][wn * 4 + tq] = s2;
        }
    }
    __syncthreads();

    if (tid < GM) {
        float A_[4] = {-1.f, -1.f, -1.f, -1.f};
        int   S_[4] = {0, 0, 0, 0};
        #pragma unroll
        for (int t = 0; t < 16; ++t) {
            #pragma unroll
            for (int slot = 0; slot < 2; ++slot) {
                float a = s_cabs[slot][tid][t];
                int sg = s_csig[slot][tid][t];
                if (a > A_[3]) {
                    if (a > A_[0]) {
                        A_[3]=A_[2]; S_[3]=S_[2]; A_[2]=A_[1]; S_[2]=S_[1];
                        A_[1]=A_[0]; S_[1]=S_[0]; A_[0]=a; S_[0]=sg;
                    } else if (a > A_[1]) {
                        A_[3]=A_[2]; S_[3]=S_[2]; A_[2]=A_[1]; S_[2]=S_[1];
                        A_[1]=a; S_[1]=sg;
                    } else if (a > A_[2]) {
                        A_[3]=A_[2]; S_[3]=S_[2]; A_[2]=a; S_[2]=sg;
                    } else {
                        A_[3]=a; S_[3]=sg;
                    }
                }
            }
        }
        #pragma unroll
        for (int s = 0; s < 4; ++s) {
            g_pA[(cb * 4 + s) * BROWS + rowbase + tid] = A_[s];
            g_pS[(cb * 4 + s) * BROWS + rowbase + tid] = S_[s];
        }
    }
}

// ---------------- Gram: G = C * C^T (fp16 mma, fp32 out), one-time ----------------
__global__ __launch_bounds__(GTHREADS, 1)
void lex_gram() {
    extern __shared__ char dsm[];
    const int tid = threadIdx.x;
    const int wid = tid >> 5;
    const int lane = tid & 31;
    const int tg = lane >> 2;
    const int tq = lane & 3;
    const int wm = wid >> 2;
    const int wn = wid & 3;
    const int rowblock = blockIdx.x >> 4;
    const int cb = blockIdx.x & 15;
    const int rowbase = rowblock * GM;
    const int colbase = cb * GN;
    const uint32_t sbase = smem_u32(dsm);

    auto issue = [&](int c) {
        const int dbase = c * 32;
        const uint32_t base = sbase + (uint32_t)(c % STAGES) * STAGEB;
        {
            int r = tid >> 2, c16 = tid & 3;
            cpasync16(base + (uint32_t)(r * AROWB + c16 * 16),
                      g_Bh + (size_t)(rowbase + r) * DDIM + dbase + c16 * 8);
        }
        #pragma unroll
        for (int i = 0; i < 2; ++i) {
            int idx = tid + i * GTHREADS;
            int n = idx >> 2, c16 = idx & 3;
            cpasync16(base + ABYTES + (uint32_t)(n * BROWB + c16 * 16),
                      g_Bh + (size_t)(colbase + n) * DDIM + dbase + c16 * 8);
        }
        CP_COMMIT();
    };

    float acc[2][8][4];
    #pragma unroll
    for (int i = 0; i < 2; ++i)
        #pragma unroll
        for (int j = 0; j < 8; ++j)
            #pragma unroll
            for (int r = 0; r < 4; ++r) acc[i][j][r] = 0.f;

    issue(0); issue(1);

    for (int c = 0; c < NCHUNKS; ++c) {
        asm volatile("cp.async.wait_group 1;" ::: "memory");
        __syncthreads();
        if (c + 2 < NCHUNKS) issue(c + 2);
        else CP_COMMIT();

        const char* As = dsm + (size_t)(c % STAGES) * STAGEB;
        const char* Bs = As + ABYTES;

        #pragma unroll
        for (int ks = 0; ks < 2; ++ks) {
            const int koff = ks * 32;
            uint32_t ah[2][4];
            #pragma unroll
            for (int i = 0; i < 2; ++i) {
                const char* p = As + (wm * 32 + i * 16 + tg) * AROWB + koff + tq * 4;
                ah[i][0] = *(const uint32_t*)(p);
                ah[i][1] = *(const uint32_t*)(p + 8 * AROWB);
                ah[i][2] = *(const uint32_t*)(p + 16);
                ah[i][3] = *(const uint32_t*)(p + 8 * AROWB + 16);
            }
            uint32_t bh[8][2];
            #pragma unroll
            for (int j = 0; j < 8; ++j) {
                const char* p = Bs + (wn * 64 + j * 8 + tg) * BROWB + koff + tq * 4;
                bh[j][0] = *(const uint32_t*)(p);
                bh[j][1] = *(const uint32_t*)(p + 16);
            }
            #pragma unroll
            for (int i = 0; i < 2; ++i)
                #pragma unroll
                for (int j = 0; j < 8; ++j)
                    mma_f16(acc[i][j], ah[i], bh[j]);
        }
    }

    #pragma unroll
    for (int i = 0; i < 2; ++i)
        #pragma unroll
        for (int h = 0; h < 2; ++h) {
            int rg = rowbase + wm * 32 + i * 16 + tg + 8 * h;
            float* gp = g_G + (size_t)rg * KDIM + colbase + wn * 64 + tq * 2;
            #pragma unroll
            for (int j = 0; j < 8; ++j)
                *(float2*)(gp + j * 8) = make_float2(acc[i][j][h * 2], acc[i][j][h * 2 + 1]);
        }
}

// ---------------- step 0: merge + exact rescore + residual update ----------------
__global__ __launch_bounds__(256)
void lex_update(const float* __restrict__ targets, const float* __restrict__ codebook,
                float* __restrict__ out, int step, float decay) {
    __shared__ int   s_k[4][64];
    __shared__ int   s_act[64];
    __shared__ float s_coef[64];
    __shared__ int   s_kidx[64];
    const int tid = threadIdx.x;
    const int rowbase = blockIdx.x * 64;
    const float* src = targets;

    if (tid < 64) {
        int row = rowbase + tid;
        float A_[4] = {-1.f, -1.f, -1.f, -1.f};
        int   K_[4] = {0, 0, 0, 0};
        #pragma unroll
        for (int cbi = 0; cbi < NCB; ++cbi) {
            #pragma unroll
            for (int slot = 0; slot < 4; ++slot) {
                float a = g_pA[(cbi * 4 + slot) * BROWS + row];
                int sg = g_pS[(cbi * 4 + slot) * BROWS + row];
                int k = (sg >= 0) ? sg : (-sg - 1);
                if (a > A_[3]) {
                    if (a > A_[0]) {
                        A_[3]=A_[2]; K_[3]=K_[2]; A_[2]=A_[1]; K_[2]=K_[1];
                        A_[1]=A_[0]; K_[1]=K_[0]; A_[0]=a; K_[0]=k;
                    } else if (a > A_[1]) {
                        A_[3]=A_[2]; K_[3]=K_[2]; A_[2]=A_[1]; K_[2]=K_[1];
                        A_[1]=a; K_[1]=k;
                    } else if (a > A_[2]) {
                        A_[3]=A_[2]; K_[3]=K_[2]; A_[2]=a; K_[2]=k;
                    } else {
                        A_[3]=a; K_[3]=k;
                    }
                }
            }
        }
        #pragma unroll
        for (int s = 0; s < 4; ++s) s_k[s][tid] = K_[s];
        s_act[tid] = (g_rnorm[row] >= 0.01f) && (g_tnorm[row] >= 1e-8f);
    }
    __syncthreads();

    const int m = tid >> 2, q = tid & 3;
    const int row = rowbase + m;
    const int k0 = s_k[0][m], k1 = s_k[1][m], k2 = s_k[2][m], k3 = s_k[3][m];
    {
        const float* rp = src + (size_t)row * DDIM + q * 128;
        const float* c0 = codebook + (size_t)k0 * DDIM + q * 128;
        const float* c1 = codebook + (size_t)k1 * DDIM + q * 128;
        const float* c2 = codebook + (size_t)k2 * DDIM + q * 128;
        const float* c3 = codebook + (size_t)k3 * DDIM + q * 128;
        float d0 = 0.f, d1 = 0.f, d2 = 0.f, d3 = 0.f;
        #pragma unroll 4
        for (int i = 0; i < 32; ++i) {
            float4 r4 = *(const float4*)(rp + i * 4);
            float4 v0 = *(const float4*)(c0 + i * 4);
            float4 v1 = *(const float4*)(c1 + i * 4);
            float4 v2 = *(const float4*)(c2 + i * 4);
            float4 v3 = *(const float4*)(c3 + i * 4);
            d0 += r4.x * v0.x + r4.y * v0.y + r4.z * v0.z + r4.w * v0.w;
            d1 += r4.x * v1.x + r4.y * v1.y + r4.z * v1.z + r4.w * v1.w;
            d2 += r4.x * v2.x + r4.y * v2.y + r4.z * v2.z + r4.w * v2.w;
            d3 += r4.x * v3.x + r4.y * v3.y + r4.z * v3.z + r4.w * v3.w;
        }
        d0 += __shfl_xor_sync(0xffffffffu, d0, 1); d0 += __shfl_xor_sync(0xffffffffu, d0, 2);
        d1 += __shfl_xor_sync(0xffffffffu, d1, 1); d1 += __shfl_xor_sync(0xffffffffu, d1, 2);
        d2 += __shfl_xor_sync(0xffffffffu, d2, 1); d2 += __shfl_xor_sync(0xffffffffu, d2, 2);
        d3 += __shfl_xor_sync(0xffffffffu, d3, 1); d3 += __shfl_xor_sync(0xffffffffu, d3, 2);
        if (q == 0) {
            float bD = d0; int bK = k0; float bA = fabsf(d0);
            float a1 = fabsf(d1);
            if (a1 > bA || (a1 == bA && k1 < bK)) { bA = a1; bD = d1; bK = k1; }
            float a2 = fabsf(d2);
            if (a2 > bA || (a2 == bA && k2 < bK)) { bA = a2; bD = d2; bK = k2; }
            float a3 = fabsf(d3);
            if (a3 > bA || (a3 == bA && k3 < bK)) { bA = a3; bD = d3; bK = k3; }
            int bS = (bD >= 0.f) ? bK : -(bK + 1);
            bool active = s_act[m];
            float coef = active ? ((bD >= 0.f) ? decay : -decay) : 0.f;
            s_coef[m] = coef;
            s_kidx[m] = bK;
            g_kprev[row] = bK;
            g_coef[row] = coef;
            out[(size_t)row * LSTEPS + step] = active ? (float)bS : 0.f;
            out[(size_t)BROWS * LSTEPS + (size_t)row * LSTEPS + step] = active ? 1.f : 0.f;
        }
    }
    __syncthreads();

    const float coef = s_coef[m];
    const int kk = s_kidx[m];
    const size_t base = (size_t)row * DDIM + q * 128;
    const size_t cbo = (size_t)kk * DDIM + q * 128;
    float sum = 0.f;
    #pragma unroll 8
    for (int i = 0; i < 32; ++i) {
        float4 r4 = *(const float4*)(src + base + i * 4);
        float4 c4 = *(const float4*)(codebook + cbo + i * 4);
        float4 o;
        o.x = r4.x - coef * c4.x;
        o.y = r4.y - coef * c4.y;
        o.z = r4.z - coef * c4.z;
        o.w = r4.w - coef * c4.w;
        sum += o.x * o.x + o.y * o.y + o.z * o.z + o.w * o.w;
        *(float4*)(g_resid + base + i * 4) = o;
    }
    sum += __shfl_xor_sync(0xffffffffu, sum, 1);
    sum += __shfl_xor_sync(0xffffffffu, sum, 2);
    if (q == 0) g_rnorm[row] = sqrtf(sum);
}

// ---------------- steps 1..15 fused: scores resident in SMEM ----------------
__global__ __launch_bounds__(256)
void lex_steps(const float* __restrict__ codebook, float* __restrict__ out) {
    __shared__ float s_sc[RPB][KDIM];     // 32 KB
    __shared__ float s_res[RPB][DDIM];    // 4 KB
    __shared__ float s_ca[RPB][8];
    __shared__ int   s_ck[RPB][8];
    __shared__ int   s_k4[RPB][4];
    __shared__ float s_d[RPB][4];
    __shared__ float s_nrm[RPB][4];
    __shared__ float s_coefS[RPB];
    __shared__ int   s_kidS[RPB];
    __shared__ float s_rn[RPB];

    const int tid = threadIdx.x;
    const int r = tid >> 7;            // 0..1
    const int t = tid & 127;
    const int w = t >> 5;
    const int lane = t & 31;
    const int row = blockIdx.x * RPB + r;

    // load scores + residual into smem
    {
        const float* sp = g_scores + (size_t)row * KDIM;
        #pragma unroll
        for (int i = 0; i < 8; ++i) {
            int k4 = (t + 128 * i) * 4;
            *(float4*)&s_sc[r][k4] = *(const float4*)(sp + k4);
        }
        *(float4*)&s_res[r][t * 4] = *(const float4*)(g_resid + (size_t)row * DDIM + t * 4);
    }
    float coefp = g_coef[row];
    int   kprev = g_kprev[row];
    float rnorm = g_rnorm[row];
    const float tnorm = g_tnorm[row];
    __syncthreads();

    float decay = 0.95f;
    for (int step = 1; step < LSTEPS; ++step) {
        decay *= 0.95f;

        // phase 1: score AXPY from G row + per-thread top-2
        const float* grow = g_G + (size_t)kprev * KDIM;
        float a1 = -1.f, a2 = -1.f; int k1 = 0, k2 = 0;
        #pragma unroll
        for (int i = 0; i < 8; ++i) {
            int k4 = (t + 128 * i) * 4;
            float4 g4 = *(const float4*)(grow + k4);
            float4 s4 = *(float4*)&s_sc[r][k4];
            s4.x -= coefp * g4.x;
            s4.y -= coefp * g4.y;
            s4.z -= coefp * g4.z;
            s4.w -= coefp * g4.w;
            *(float4*)&s_sc[r][k4] = s4;
            float av;
            av = fabsf(s4.x); if (av > a1) { a2=a1;k2=k1; a1=av;k1=k4;   } else if (av > a2) { a2=av;k2=k4;   }
            av = fabsf(s4.y); if (av > a1) { a2=a1;k2=k1; a1=av;k1=k4+1; } else if (av > a2) { a2=av;k2=k4+1; }
            av = fabsf(s4.z); if (av > a1) { a2=a1;k2=k1; a1=av;k1=k4+2; } else if (av > a2) { a2=av;k2=k4+2; }
            av = fabsf(s4.w); if (av > a1) { a2=a1;k2=k1; a1=av;k1=k4+3; } else if (av > a2) { a2=av;k2=k4+3; }
        }
        #pragma unroll
        for (int off = 1; off < 32; off <<= 1) {
            float b1 = __shfl_xor_sync(0xffffffffu, a1, off);
            int   j1 = __shfl_xor_sync(0xffffffffu, k1, off);
            float b2 = __shfl_xor_sync(0xffffffffu, a2, off);
            int   j2 = __shfl_xor_sync(0xffffffffu, k2, off);
            bool fA = (a1 > b1) || (a1 == b1 && k1 < j1);
            float n1  = fA ? a1 : b1;  int n1k  = fA ? k1 : j1;
            float c2  = fA ? b1 : a1;  int c2k  = fA ? j1 : k1;
            float alt = fA ? a2 : b2;  int altk = fA ? k2 : j2;
            bool s2A = (c2 > alt) || (c2 == alt && c2k < altk);
            a1 = n1; k1 = n1k;
            a2 = s2A ? c2 : alt; k2 = s2A ? c2k : altk;
        }
        if (lane == 0) {
            s_ca[r][w * 2]     = a1; s_ck[r][w * 2]     = k1;
            s_ca[r][w * 2 + 1] = a2; s_ck[r][w * 2 + 1] = k2;
        }
        __syncthreads();

        if (t == 0) {
            float A_[4] = {-1.f, -1.f, -1.f, -1.f};
            int   K_[4] = {0, 0, 0, 0};
            #pragma unroll
            for (int e = 0; e < 8; ++e) {
                float a = s_ca[r][e]; int k = s_ck[r][e];
                if (a > A_[3] || (a == A_[3] && k < K_[3])) {
                    if (a > A_[0] || (a == A_[0] && k < K_[0])) {
                        A_[3]=A_[2]; K_[3]=K_[2]; A_[2]=A_[1]; K_[2]=K_[1];
                        A_[1]=A_[0]; K_[1]=K_[0]; A_[0]=a; K_[0]=k;
                    } else if (a > A_[1] || (a == A_[1] && k < K_[1])) {
                        A_[3]=A_[2]; K_[3]=K_[2]; A_[2]=A_[1]; K_[2]=K_[1];
                        A_[1]=a; K_[1]=k;
                    } else if (a > A_[2] || (a == A_[2] && k < K_[2])) {
                        A_[3]=A_[2]; K_[3]=K_[2]; A_[2]=a; K_[2]=k;
                    } else {
                        A_[3]=a; K_[3]=k;
                    }
                }
            }
            #pragma unroll
            for (int s = 0; s < 4; ++s) s_k4[r][s] = K_[s];
        }
        __syncthreads();

        // phase 2: exact fp32 rescore (warp w -> candidate w), residual from smem
        {
            int kc = s_k4[r][w];
            const float* cp = codebook + (size_t)kc * DDIM;
            float d = 0.f;
            #pragma unroll
            for (int ii = 0; ii < 4; ++ii) {
                int idx = (lane + 32 * ii) * 4;
                float4 r4 = *(float4*)&s_res[r][idx];
                float4 c4 = *(const float4*)(cp + idx);
                d += r4.x * c4.x + r4.y * c4.y + r4.z * c4.z + r4.w * c4.w;
            }
            #pragma unroll
            for (int off = 16; off; off >>= 1) d += __shfl_xor_sync(0xffffffffu, d, off);
            if (lane == 0) s_d[r][w] = d;
        }
        __syncthreads();

        if (t == 0) {
            float bD = s_d[r][0]; int bK = s_k4[r][0]; float bA = fabsf(bD);
            #pragma unroll
            for (int c = 1; c < 4; ++c) {
                float dd = s_d[r][c]; float aa = fabsf(dd); int kk2 = s_k4[r][c];
                if (aa > bA || (aa == bA && kk2 < bK)) { bA = aa; bD = dd; bK = kk2; }
            }
            bool active = (rnorm >= 0.01f) && (tnorm >= 1e-8f);
            float coef = active ? ((bD >= 0.f) ? decay : -decay) : 0.f;
            int bS = (bD >= 0.f) ? bK : -(bK + 1);
            s_coefS[r] = coef; s_kidS[r] = bK;
            out[(size_t)row * LSTEPS + step] = active ? (float)bS : 0.f;
            out[(size_t)BROWS * LSTEPS + (size_t)row * LSTEPS + step] = active ? 1.f : 0.f;
        }
        __syncthreads();

        // phase 3: residual update in smem + norm
        {
            const float coef = s_coefS[r];
            const int kk = s_kidS[r];
            float4 r4 = *(float4*)&s_res[r][t * 4];
            float4 c4 = *(const float4*)(codebook + (size_t)kk * DDIM + t * 4);
            float4 o;
            o.x = r4.x - coef * c4.x;
            o.y = r4.y - coef * c4.y;
            o.z = r4.z - coef * c4.z;
            o.w = r4.w - coef * c4.w;
            *(float4*)&s_res[r][t * 4] = o;
            float s = o.x * o.x + o.y * o.y + o.z * o.z + o.w * o.w;
            #pragma unroll
            for (int off = 16; off; off >>= 1) s += __shfl_xor_sync(0xffffffffu, s, off);
            if (lane == 0) s_nrm[r][w] = s;
        }
        __syncthreads();
        if (t == 0)
            s_rn[r] = sqrtf(s_nrm[r][0] + s_nrm[r][1] + s_nrm[r][2] + s_nrm[r][3]);
        __syncthreads();
        rnorm = s_rn[r];
        kprev = s_kidS[r];
        coefp = s_coefS[r];
    }

    // final residual write
    *(float4*)(out + 2 * (size_t)BROWS * LSTEPS + (size_t)row * DDIM + t * 4) =
        *(float4*)&s_res[r][t * 4];
}

extern "C" void kernel_launch(void* const* d_in, const int* in_sizes, int n_in,
                              void* d_out, int out_size) {
    (void)n_in; (void)out_size;
    const float* targets;
    const float* codebook;
    if (in_sizes[0] == BROWS * DDIM) {
        targets  = (const float*)d_in[0];
        codebook = (const float*)d_in[1];
    } else {
        targets  = (const float*)d_in[1];
        codebook = (const float*)d_in[0];
    }
    cudaFuncSetAttribute(lex_gemm, cudaFuncAttributeMaxDynamicSharedMemorySize, SMEM_DYN);
    cudaFuncSetAttribute(lex_gram, cudaFuncAttributeMaxDynamicSharedMemorySize, SMEM_DYN);
    float* out = (float*)d_out;

    lex_prep<<<192, 256>>>(targets, codebook);
    lex_gram<<<(KDIM / GM) * (KDIM / GN), GTHREADS, SMEM_DYN>>>();
    lex_gemm<<<(BROWS / GM) * NCB, GTHREADS, SMEM_DYN>>>();
    lex_update<<<BROWS / 64, 256>>>(targets, codebook, out, 0, 0.95f);
    lex_steps<<<BROWS / RPB, 256>>>(codebook, out);
}